// round 7
// baseline (speedup 1.0000x reference)
#include <cuda_runtime.h>
#include <math_constants.h>
#include <cstdint>

#define NH    16
#define HD    64
#define SEQ   1024
#define BATCH 4
#define HID   1024

// scratch: Q/K/V in [b, h, s, d] layout (16 MB each)
__device__ float g_Q[BATCH * NH * SEQ * HD];
__device__ float g_K[BATCH * NH * SEQ * HD];
__device__ float g_V[BATCH * NH * SEQ * HD];

// ===========================================================================
// packed fp32x2 helpers
// ===========================================================================
typedef unsigned long long u64;

__device__ __forceinline__ u64 f2pack(float lo, float hi) {
    u64 r; asm("mov.b64 %0, {%1, %2};" : "=l"(r) : "f"(lo), "f"(hi)); return r;
}
__device__ __forceinline__ void f2unpack(u64 v, float& lo, float& hi) {
    asm("mov.b64 {%0, %1}, %2;" : "=f"(lo), "=f"(hi) : "l"(v));
}
__device__ __forceinline__ u64 f2add(u64 a, u64 b) {
    u64 r; asm("add.rn.f32x2 %0, %1, %2;" : "=l"(r) : "l"(a), "l"(b)); return r;
}
__device__ __forceinline__ u64 f2mul(u64 a, u64 b) {
    u64 r; asm("mul.rn.f32x2 %0, %1, %2;" : "=l"(r) : "l"(a), "l"(b)); return r;
}
__device__ __forceinline__ u64 f2fma(u64 a, u64 b, u64 c) {
    u64 r; asm("fma.rn.f32x2 %0, %1, %2, %3;" : "=l"(r) : "l"(a), "l"(b), "l"(c)); return r;
}

// ===========================================================================
// Kernel 1: fused QKV projection via mma.sync tf32 (unchanged — WIN from R4)
// ===========================================================================
#define SST 36
#define QG_BUF_FLOATS (128 * SST)
#define QG_SMEM_B (4 * QG_BUF_FLOATS * 4)

__device__ __forceinline__ float tf32r(float x) {
    uint32_t u;
    asm("cvt.rna.tf32.f32 %0, %1;" : "=r"(u) : "f"(x));
    return __uint_as_float(u);
}

__device__ __forceinline__ void mma16n8k8(float c[4], const uint32_t a[4],
                                          const uint32_t b[2]) {
    asm volatile(
        "mma.sync.aligned.m16n8k8.row.col.f32.tf32.tf32.f32 "
        "{%0,%1,%2,%3}, {%4,%5,%6,%7}, {%8,%9}, {%0,%1,%2,%3};"
        : "+f"(c[0]), "+f"(c[1]), "+f"(c[2]), "+f"(c[3])
        : "r"(a[0]), "r"(a[1]), "r"(a[2]), "r"(a[3]), "r"(b[0]), "r"(b[1]));
}

__global__ __launch_bounds__(256) void qkv_gemm_mma(
    const float* __restrict__ hs,
    const float* __restrict__ w,
    const float* __restrict__ bias)
{
    extern __shared__ __align__(16) float sm[];
    float* As = sm;
    float* Bs = sm + 2 * QG_BUF_FLOATS;

    const int tid  = threadIdx.x;
    const int m0   = blockIdx.y * 128;
    const int n0   = blockIdx.x * 128;
    const int lrow = tid >> 3;
    const int lc4  = tid & 7;

    const int lane = tid & 31, g = lane >> 2, t = lane & 3;
    const int wid  = tid >> 5, wm = wid >> 2, wn = wid & 3;

    float4 ra[4], rb[4];

#pragma unroll
    for (int it = 0; it < 4; ++it) {
        const int row = lrow + it * 32;
        ra[it] = *(const float4*)(hs + (size_t)(m0 + row) * HID + lc4 * 4);
        rb[it] = *(const float4*)(w  + (size_t)(n0 + row) * HID + lc4 * 4);
    }
#pragma unroll
    for (int it = 0; it < 4; ++it) {
        const int row = lrow + it * 32;
        float4 va = make_float4(tf32r(ra[it].x), tf32r(ra[it].y),
                                tf32r(ra[it].z), tf32r(ra[it].w));
        float4 vb = make_float4(tf32r(rb[it].x), tf32r(rb[it].y),
                                tf32r(rb[it].z), tf32r(rb[it].w));
        *(float4*)(As + row * SST + lc4 * 4) = va;
        *(float4*)(Bs + row * SST + lc4 * 4) = vb;
    }
    __syncthreads();

    float c[4][4][4];
#pragma unroll
    for (int mi = 0; mi < 4; ++mi)
#pragma unroll
        for (int ni = 0; ni < 4; ++ni)
#pragma unroll
            for (int r = 0; r < 4; ++r) c[mi][ni][r] = 0.f;

    for (int ch = 0; ch < 32; ++ch) {
        const int p = ch & 1;
        if (ch < 31) {
            const int k0 = (ch + 1) * 32;
#pragma unroll
            for (int it = 0; it < 4; ++it) {
                const int row = lrow + it * 32;
                ra[it] = *(const float4*)(hs + (size_t)(m0 + row) * HID + k0 + lc4 * 4);
                rb[it] = *(const float4*)(w  + (size_t)(n0 + row) * HID + k0 + lc4 * 4);
            }
        }

        const float* Ab = As + p * QG_BUF_FLOATS;
        const float* Bb = Bs + p * QG_BUF_FLOATS;
#pragma unroll
        for (int ks = 0; ks < 4; ++ks) {
            const int kc = ks * 8 + t;
            uint32_t a[4][4], b[4][2];
#pragma unroll
            for (int mi = 0; mi < 4; ++mi) {
                const float* ap = Ab + (wm * 64 + mi * 16 + g) * SST + kc;
                a[mi][0] = __float_as_uint(ap[0]);
                a[mi][1] = __float_as_uint(ap[8 * SST]);
                a[mi][2] = __float_as_uint(ap[4]);
                a[mi][3] = __float_as_uint(ap[8 * SST + 4]);
            }
#pragma unroll
            for (int ni = 0; ni < 4; ++ni) {
                const float* bp = Bb + (wn * 32 + ni * 8 + g) * SST + kc;
                b[ni][0] = __float_as_uint(bp[0]);
                b[ni][1] = __float_as_uint(bp[4]);
            }
#pragma unroll
            for (int mi = 0; mi < 4; ++mi)
#pragma unroll
                for (int ni = 0; ni < 4; ++ni)
                    mma16n8k8(c[mi][ni], a[mi], b[ni]);
        }

        if (ch < 31) {
            float* An = As + ((ch + 1) & 1) * QG_BUF_FLOATS;
            float* Bn = Bs + ((ch + 1) & 1) * QG_BUF_FLOATS;
#pragma unroll
            for (int it = 0; it < 4; ++it) {
                const int row = lrow + it * 32;
                float4 va = make_float4(tf32r(ra[it].x), tf32r(ra[it].y),
                                        tf32r(ra[it].z), tf32r(ra[it].w));
                float4 vb = make_float4(tf32r(rb[it].x), tf32r(rb[it].y),
                                        tf32r(rb[it].z), tf32r(rb[it].w));
                *(float4*)(An + row * SST + lc4 * 4) = va;
                *(float4*)(Bn + row * SST + lc4 * 4) = vb;
            }
        }
        __syncthreads();
    }

    const int tsel = n0 >> 10;
    float* dst = (tsel == 0) ? g_Q : (tsel == 1) ? g_K : g_V;
#pragma unroll
    for (int mi = 0; mi < 4; ++mi) {
        const int m  = m0 + wm * 64 + mi * 16 + g;
        const int bb = m >> 10;
        const int s  = m & 1023;
#pragma unroll
        for (int ni = 0; ni < 4; ++ni) {
            const int gn  = n0 + wn * 32 + ni * 8 + t * 2;
            const int rem = gn & 1023;
            const int hh  = rem >> 6;
            const int dd  = rem & 63;
            const float2 bi = *(const float2*)(bias + gn);
            float* base = dst + ((size_t)(bb * NH + hh) * SEQ + s) * HD + dd;
            float2 v0 = make_float2(c[mi][ni][0] + bi.x, c[mi][ni][1] + bi.y);
            float2 v1 = make_float2(c[mi][ni][2] + bi.x, c[mi][ni][3] + bi.y);
            *(float2*)(base) = v0;
            *(float2*)(base + 8 * HD) = v1;
        }
    }
}

// ---------------------------------------------------------------------------
// Kernel 2: attention. 256 threads, 3 blocks/SM (smem cut to ~68.6 KB):
//   - V read directly from gmem in PV (natural layout, coalesced, L1/L2 hot)
//   - Pp (packed P) aliased into Et (dead after score loop; extra barrier)
// ---------------------------------------------------------------------------
#define QT_STRIDE 68
#define ET_STRIDE 132
#define PP_STRIDE 33   // u64 units per j-row
#define ATTN_SMEM_FLOATS (64*QT_STRIDE*2 + 64*ET_STRIDE)

__global__ __launch_bounds__(256, 3) void attn_kernel(
    const float* __restrict__ emb,
    const float* __restrict__ mask,
    float* __restrict__ out)
{
    extern __shared__ __align__(16) float sm2[];
    float* Qt  = sm2;                      // [64 dd][68]
    float* Kt  = Qt + 64 * QT_STRIDE;      // [64 dd][68]
    float* Et  = Kt + 64 * QT_STRIDE;      // [64 dd][132]
    u64*   Pp  = (u64*)Et;                 // alias: [64 j][33] (Et dead post-score)

    const int tid = threadIdx.x;
    const int ti  = tid >> 4;   // 0..15 -> rows i0 = ti*4
    const int tj  = tid & 15;   // 0..15 -> cols j0 = tj*4
    const int bh  = blockIdx.y;
    const int b   = bh >> 4;
    const int hh  = bh & 15;
    const int l0  = blockIdx.x * 64;

    const float* Qg = g_Q + ((size_t)bh * SEQ + l0) * HD;
    for (int idx = tid; idx < 64 * 64; idx += 256) {
        const int i = idx >> 6, dd = idx & 63;
        Qt[dd * QT_STRIDE + i] = Qg[idx];
    }

    float mrow[4], lsum[4];
    u64 acc[2][4];
#pragma unroll
    for (int a = 0; a < 4; a++) { mrow[a] = -CUDART_INF_F; lsum[a] = 0.f; }
#pragma unroll
    for (int a2 = 0; a2 < 2; a2++)
#pragma unroll
        for (int c = 0; c < 4; c++) acc[a2][c] = 0ull;

    const int ibase = ti * 4 - tj * 4 + 60;

    for (int r0 = 0; r0 < SEQ; r0 += 64) {
        const float* Kg = g_K + ((size_t)bh * SEQ + r0) * HD;
        const float* Vg = g_V + ((size_t)bh * SEQ + r0) * HD;
        const int gb_ = l0 - r0 + 960;

        __syncthreads();   // prev PV (reads Pp/Et alias) done before overwrite
        for (int idx = tid; idx < 64 * 64; idx += 256) {
            const int i = idx >> 6, dd = idx & 63;
            Kt[dd * QT_STRIDE + i] = Kg[idx];
        }
        for (int idx = tid; idx < 127 * 64; idx += 256) {
            const int ib = idx >> 6, dd = idx & 63;
            Et[dd * ET_STRIDE + ib] = emb[(size_t)(gb_ + ib) * HD + dd];
        }
        __syncthreads();

        // ---- score tile ----
        u64 s2[2][4];
#pragma unroll
        for (int a2 = 0; a2 < 2; a2++)
#pragma unroll
            for (int c = 0; c < 4; c++) s2[a2][c] = 0ull;

#pragma unroll 2
        for (int dd = 0; dd < 64; dd++) {
            const ulonglong2 qA = *(const ulonglong2*)&Qt[dd * QT_STRIDE + ti * 4];
            const u64 qp[2] = {qA.x, qA.y};

            const float4 kv = *(const float4*)&Kt[dd * QT_STRIDE + tj * 4];
            u64 kb[4];
            kb[0] = f2pack(kv.x, kv.x); kb[1] = f2pack(kv.y, kv.y);
            kb[2] = f2pack(kv.z, kv.z); kb[3] = f2pack(kv.w, kv.w);

            const float* er = &Et[dd * ET_STRIDE + ibase];
            const float4 e0 = *(const float4*)(er);
            const float4 e1 = *(const float4*)(er + 4);
            const float e[8] = {e0.x, e0.y, e0.z, e0.w, e1.x, e1.y, e1.z, e1.w};
            u64 P[6];
#pragma unroll
            for (int m = 0; m < 6; m++) P[m] = f2pack(e[m], e[m + 1]);

#pragma unroll
            for (int a2 = 0; a2 < 2; a2++)
#pragma unroll
                for (int c = 0; c < 4; c++) {
                    s2[a2][c] = f2fma(qp[a2], kb[c], s2[a2][c]);
                    const u64 t = f2add(qp[a2], kb[c]);
                    s2[a2][c] = f2fma(t, P[2 * a2 - c + 3], s2[a2][c]);
                }
        }

        // ---- unpack, scale + mask ----
        float s[4][4];
#pragma unroll
        for (int a2 = 0; a2 < 2; a2++)
#pragma unroll
            for (int c = 0; c < 4; c++)
                f2unpack(s2[a2][c], s[2 * a2][c], s[2 * a2 + 1][c]);

        float mk[4];
#pragma unroll
        for (int c = 0; c < 4; c++) mk[c] = mask[b * SEQ + r0 + tj * 4 + c];
#pragma unroll
        for (int a = 0; a < 4; a++)
#pragma unroll
            for (int c = 0; c < 4; c++)
                s[a][c] = s[a][c] * 0.125f + mk[c];

        // ---- online softmax ----
        float pall[4][4], corr[4];
#pragma unroll
        for (int a = 0; a < 4; a++) {
            float pm = fmaxf(fmaxf(s[a][0], s[a][1]), fmaxf(s[a][2], s[a][3]));
#pragma unroll
            for (int off = 8; off > 0; off >>= 1)
                pm = fmaxf(pm, __shfl_xor_sync(0xffffffffu, pm, off));
            const float mnew = fmaxf(mrow[a], pm);
            corr[a] = __expf(mrow[a] - mnew);
            mrow[a] = mnew;
            float ps = 0.f;
#pragma unroll
            for (int c = 0; c < 4; c++) { pall[a][c] = __expf(s[a][c] - mnew); ps += pall[a][c]; }
#pragma unroll
            for (int off = 8; off > 0; off >>= 1)
                ps += __shfl_xor_sync(0xffffffffu, ps, off);
            lsum[a] = lsum[a] * corr[a] + ps;
        }

        __syncthreads();   // all score-loop reads of Et done before Pp overwrite

#pragma unroll
        for (int a2 = 0; a2 < 2; a2++) {
            const u64 cc = f2pack(corr[2 * a2], corr[2 * a2 + 1]);
#pragma unroll
            for (int c = 0; c < 4; c++) acc[a2][c] = f2mul(acc[a2][c], cc);
#pragma unroll
            for (int c = 0; c < 4; c++)
                Pp[(tj * 4 + c) * PP_STRIDE + ti * 2 + a2] =
                    f2pack(pall[2 * a2][c], pall[2 * a2 + 1][c]);
        }
        __syncthreads();

        // ---- P @ V (V direct from gmem: natural [j][dd] layout, coalesced) ----
#pragma unroll 2
        for (int j = 0; j < 64; j++) {
            const float4 vv = *(const float4*)(Vg + j * HD + tj * 4);
            u64 vb[4];
            vb[0] = f2pack(vv.x, vv.x); vb[1] = f2pack(vv.y, vv.y);
            vb[2] = f2pack(vv.z, vv.z); vb[3] = f2pack(vv.w, vv.w);
            const u64 pp0 = Pp[j * PP_STRIDE + ti * 2 + 0];
            const u64 pp1 = Pp[j * PP_STRIDE + ti * 2 + 1];
#pragma unroll
            for (int c = 0; c < 4; c++) {
                acc[0][c] = f2fma(pp0, vb[c], acc[0][c]);
                acc[1][c] = f2fma(pp1, vb[c], acc[1][c]);
            }
        }
    }

    // ---- write context ----
#pragma unroll
    for (int a2 = 0; a2 < 2; a2++) {
        float lo[4], hi[4];
#pragma unroll
        for (int c = 0; c < 4; c++) f2unpack(acc[a2][c], lo[c], hi[c]);
        const float inv0 = 1.f / lsum[2 * a2];
        const float inv1 = 1.f / lsum[2 * a2 + 1];
        const int l = l0 + ti * 4 + 2 * a2;
        *(float4*)(out + (size_t)(b * SEQ + l) * HID + hh * HD + tj * 4) =
            make_float4(lo[0] * inv0, lo[1] * inv0, lo[2] * inv0, lo[3] * inv0);
        *(float4*)(out + (size_t)(b * SEQ + l + 1) * HID + hh * HD + tj * 4) =
            make_float4(hi[0] * inv1, hi[1] * inv1, hi[2] * inv1, hi[3] * inv1);
    }
}

// ---------------------------------------------------------------------------
extern "C" void kernel_launch(void* const* d_in, const int* in_sizes, int n_in,
                              void* d_out, int out_size)
{
    (void)in_sizes; (void)n_in; (void)out_size;
    const float* hs   = (const float*)d_in[0];
    const float* w    = (const float*)d_in[1];
    const float* bias = (const float*)d_in[2];
    const float* emb  = (const float*)d_in[3];
    const float* mask = (const float*)d_in[4];
    float* out = (float*)d_out;

    cudaFuncSetAttribute(qkv_gemm_mma,
                         cudaFuncAttributeMaxDynamicSharedMemorySize, QG_SMEM_B);
    qkv_gemm_mma<<<dim3(HID * 3 / 128, BATCH * SEQ / 128), 256, QG_SMEM_B>>>(hs, w, bias);

    const size_t smem = (size_t)ATTN_SMEM_FLOATS * sizeof(float);
    cudaFuncSetAttribute(attn_kernel,
                         cudaFuncAttributeMaxDynamicSharedMemorySize, (int)smem);
    attn_kernel<<<dim3(SEQ / 64, BATCH * NH), 256, smem>>>(emb, mask, out);
}

// round 8
// speedup vs baseline: 1.7732x; 1.7732x over previous
#include <cuda_runtime.h>
#include <cuda_fp16.h>
#include <math_constants.h>
#include <cstdint>

#define NH    16
#define HD    64
#define SEQ   1024
#define BATCH 4
#define HID   1024

// scratch: Q/K/V in [b, h, s, d] layout (16 MB each)
__device__ float g_Q[BATCH * NH * SEQ * HD];
__device__ float g_K[BATCH * NH * SEQ * HD];
__device__ float g_V[BATCH * NH * SEQ * HD];

__device__ __forceinline__ float tf32r(float x) {
    uint32_t u;
    asm("cvt.rna.tf32.f32 %0, %1;" : "=r"(u) : "f"(x));
    return __uint_as_float(u);
}

__device__ __forceinline__ void mma16n8k8(float c[4], const uint32_t a[4],
                                          const uint32_t b[2]) {
    asm volatile(
        "mma.sync.aligned.m16n8k8.row.col.f32.tf32.tf32.f32 "
        "{%0,%1,%2,%3}, {%4,%5,%6,%7}, {%8,%9}, {%0,%1,%2,%3};"
        : "+f"(c[0]), "+f"(c[1]), "+f"(c[2]), "+f"(c[3])
        : "r"(a[0]), "r"(a[1]), "r"(a[2]), "r"(a[3]), "r"(b[0]), "r"(b[1]));
}

// ===========================================================================
// Kernel 1: fused QKV projection via mma.sync tf32 (unchanged — WIN from R4)
// ===========================================================================
#define SST 36
#define QG_BUF_FLOATS (128 * SST)
#define QG_SMEM_B (4 * QG_BUF_FLOATS * 4)

__global__ __launch_bounds__(256) void qkv_gemm_mma(
    const float* __restrict__ hs,
    const float* __restrict__ w,
    const float* __restrict__ bias)
{
    extern __shared__ __align__(16) float sm[];
    float* As = sm;
    float* Bs = sm + 2 * QG_BUF_FLOATS;

    const int tid  = threadIdx.x;
    const int m0   = blockIdx.y * 128;
    const int n0   = blockIdx.x * 128;
    const int lrow = tid >> 3;
    const int lc4  = tid & 7;

    const int lane = tid & 31, g = lane >> 2, t = lane & 3;
    const int wid  = tid >> 5, wm = wid >> 2, wn = wid & 3;

    float4 ra[4], rb[4];

#pragma unroll
    for (int it = 0; it < 4; ++it) {
        const int row = lrow + it * 32;
        ra[it] = *(const float4*)(hs + (size_t)(m0 + row) * HID + lc4 * 4);
        rb[it] = *(const float4*)(w  + (size_t)(n0 + row) * HID + lc4 * 4);
    }
#pragma unroll
    for (int it = 0; it < 4; ++it) {
        const int row = lrow + it * 32;
        float4 va = make_float4(tf32r(ra[it].x), tf32r(ra[it].y),
                                tf32r(ra[it].z), tf32r(ra[it].w));
        float4 vb = make_float4(tf32r(rb[it].x), tf32r(rb[it].y),
                                tf32r(rb[it].z), tf32r(rb[it].w));
        *(float4*)(As + row * SST + lc4 * 4) = va;
        *(float4*)(Bs + row * SST + lc4 * 4) = vb;
    }
    __syncthreads();

    float c[4][4][4];
#pragma unroll
    for (int mi = 0; mi < 4; ++mi)
#pragma unroll
        for (int ni = 0; ni < 4; ++ni)
#pragma unroll
            for (int r = 0; r < 4; ++r) c[mi][ni][r] = 0.f;

    for (int ch = 0; ch < 32; ++ch) {
        const int p = ch & 1;
        if (ch < 31) {
            const int k0 = (ch + 1) * 32;
#pragma unroll
            for (int it = 0; it < 4; ++it) {
                const int row = lrow + it * 32;
                ra[it] = *(const float4*)(hs + (size_t)(m0 + row) * HID + k0 + lc4 * 4);
                rb[it] = *(const float4*)(w  + (size_t)(n0 + row) * HID + k0 + lc4 * 4);
            }
        }

        const float* Ab = As + p * QG_BUF_FLOATS;
        const float* Bb = Bs + p * QG_BUF_FLOATS;
#pragma unroll
        for (int ks = 0; ks < 4; ++ks) {
            const int kc = ks * 8 + t;
            uint32_t a[4][4], b[4][2];
#pragma unroll
            for (int mi = 0; mi < 4; ++mi) {
                const float* ap = Ab + (wm * 64 + mi * 16 + g) * SST + kc;
                a[mi][0] = __float_as_uint(ap[0]);
                a[mi][1] = __float_as_uint(ap[8 * SST]);
                a[mi][2] = __float_as_uint(ap[4]);
                a[mi][3] = __float_as_uint(ap[8 * SST + 4]);
            }
#pragma unroll
            for (int ni = 0; ni < 4; ++ni) {
                const float* bp = Bb + (wn * 32 + ni * 8 + g) * SST + kc;
                b[ni][0] = __float_as_uint(bp[0]);
                b[ni][1] = __float_as_uint(bp[4]);
            }
#pragma unroll
            for (int mi = 0; mi < 4; ++mi)
#pragma unroll
                for (int ni = 0; ni < 4; ++ni)
                    mma16n8k8(c[mi][ni], a[mi], b[ni]);
        }

        if (ch < 31) {
            float* An = As + ((ch + 1) & 1) * QG_BUF_FLOATS;
            float* Bn = Bs + ((ch + 1) & 1) * QG_BUF_FLOATS;
#pragma unroll
            for (int it = 0; it < 4; ++it) {
                const int row = lrow + it * 32;
                float4 va = make_float4(tf32r(ra[it].x), tf32r(ra[it].y),
                                        tf32r(ra[it].z), tf32r(ra[it].w));
                float4 vb = make_float4(tf32r(rb[it].x), tf32r(rb[it].y),
                                        tf32r(rb[it].z), tf32r(rb[it].w));
                *(float4*)(An + row * SST + lc4 * 4) = va;
                *(float4*)(Bn + row * SST + lc4 * 4) = vb;
            }
        }
        __syncthreads();
    }

    const int tsel = n0 >> 10;
    float* dst = (tsel == 0) ? g_Q : (tsel == 1) ? g_K : g_V;
#pragma unroll
    for (int mi = 0; mi < 4; ++mi) {
        const int m  = m0 + wm * 64 + mi * 16 + g;
        const int bb = m >> 10;
        const int s  = m & 1023;
#pragma unroll
        for (int ni = 0; ni < 4; ++ni) {
            const int gn  = n0 + wn * 32 + ni * 8 + t * 2;
            const int rem = gn & 1023;
            const int hh  = rem >> 6;
            const int dd  = rem & 63;
            const float2 bi = *(const float2*)(bias + gn);
            float* base = dst + ((size_t)(bb * NH + hh) * SEQ + s) * HD + dd;
            float2 v0 = make_float2(c[mi][ni][0] + bi.x, c[mi][ni][1] + bi.y);
            float2 v1 = make_float2(c[mi][ni][2] + bi.x, c[mi][ni][3] + bi.y);
            *(float2*)(base) = v0;
            *(float2*)(base + 8 * HD) = v1;
        }
    }
}

// ===========================================================================
// Kernel 2: attention fully on mma.sync tf32.
//   S = Q@K^T ; QE = Q@E^T ; KE = K@E^T  (E = 128-row dist_emb band, natural)
//   S[i,j] += QE[i, i-j+63] + KE[j, i-j+63]  (smem gather, QE/KE stored fp16)
//   flash softmax in fragments, PV = P@V^T via mma (V transposed at staging)
// Warps 0-3: QE + QK + softmax.  Warps 4-7: KE + Vt staging.  All: PV.
// smem 105216 B -> 2 blocks/SM.
// ===========================================================================
#define AT_SMEM_B 105216

__global__ __launch_bounds__(256, 2) void attn_mma(
    const float* __restrict__ emb,
    const float* __restrict__ mask,
    float* __restrict__ out)
{
    extern __shared__ __align__(16) float sm2[];
    float*  Qs    = sm2;                    // [64][68]
    float*  Ks    = sm2 + 4352;             // [64][68]  (aliased by Vt)
    float*  Vt    = Ks;
    float*  Es    = sm2 + 8704;             // [128][68] (aliased by Ps [64][68])
    float*  Ps    = Es;
    __half* QEh   = (__half*)(sm2 + 17408); // [64][136] halves
    __half* KEh   = (__half*)(sm2 + 21760); // [64][136] halves
    float*  corrs = sm2 + 26112;            // [64]
    float*  lsums = sm2 + 26176;            // [64]
    float*  maskS = sm2 + 26240;            // [64]

    const int tid  = threadIdx.x;
    const int lane = tid & 31, g = lane >> 2, t = lane & 3;
    const int wid  = tid >> 5;
    const int ms   = (wid & 3) * 16;        // m-strip (rows) for this warp
    const int nh   = (wid >> 2) * 32;       // n-half for PV
    const bool isA = (wid < 4);
    const int bh = blockIdx.y, b = bh >> 4, hh = bh & 15;
    const int l0 = blockIdx.x * 64;

    // ---- stage Q (tf32-rounded, natural [i][d]) ----
    const float* Qg = g_Q + ((size_t)bh * SEQ + l0) * HD;
#pragma unroll
    for (int it = 0; it < 4; ++it) {
        const int idx = tid * 4 + it * 1024;
        const int i = idx >> 6, dd = idx & 63;
        float4 v = *(const float4*)(Qg + idx);
        *(float4*)&Qs[i * 68 + dd] =
            make_float4(tf32r(v.x), tf32r(v.y), tf32r(v.z), tf32r(v.w));
    }

    float mrow0 = -CUDART_INF_F, mrow1 = -CUDART_INF_F;
    float lsum0 = 0.f, lsum1 = 0.f;
    float acc[4][4];
#pragma unroll
    for (int nt = 0; nt < 4; ++nt)
#pragma unroll
        for (int r = 0; r < 4; ++r) acc[nt][r] = 0.f;

    float S[8][4];

    for (int r0 = 0; r0 < SEQ; r0 += 64) {
        const int gb_ = l0 - r0 + 960;

        __syncthreads();   // sync1: prior PV (reads Ps, Vt) done
        // ---- stage K, E band, mask ----
        const float* Kg = g_K + ((size_t)bh * SEQ + r0) * HD;
#pragma unroll
        for (int it = 0; it < 4; ++it) {
            const int idx = tid * 4 + it * 1024;
            const int i = idx >> 6, dd = idx & 63;
            float4 v = *(const float4*)(Kg + idx);
            *(float4*)&Ks[i * 68 + dd] =
                make_float4(tf32r(v.x), tf32r(v.y), tf32r(v.z), tf32r(v.w));
        }
#pragma unroll
        for (int it = 0; it < 8; ++it) {
            const int idx = tid * 4 + it * 1024;
            const int r = idx >> 6, dd = idx & 63;
            const int er = min(gb_ + r, 2046);   // row 127 unused; clamp in-bounds
            float4 v = *(const float4*)(emb + (size_t)er * HD + dd);
            *(float4*)&Es[r * 68 + dd] =
                make_float4(tf32r(v.x), tf32r(v.y), tf32r(v.z), tf32r(v.w));
        }
        if (tid < 16)
            *(float4*)&maskS[tid * 4] = *(const float4*)(mask + b * SEQ + r0 + tid * 4);
        __syncthreads();   // sync2: operands ready

        // ---- mma phase: QE+QK (warps 0-3) / KE (warps 4-7) ----
        const float* Arows = isA ? Qs : Ks;       // A operand strip source
        {
            __half* dstT = isA ? QEh : KEh;
#pragma unroll
            for (int half = 0; half < 2; ++half) {
                float qe[8][4];
#pragma unroll
                for (int nt = 0; nt < 8; ++nt)
#pragma unroll
                    for (int r = 0; r < 4; ++r) qe[nt][r] = 0.f;
#pragma unroll
                for (int ks = 0; ks < 8; ++ks) {
                    const int kc = ks * 8 + t;
                    uint32_t a[4];
                    const float* ap = Arows + (ms + g) * 68 + kc;
                    a[0] = __float_as_uint(ap[0]);
                    a[1] = __float_as_uint(ap[8 * 68]);
                    a[2] = __float_as_uint(ap[4]);
                    a[3] = __float_as_uint(ap[8 * 68 + 4]);
#pragma unroll
                    for (int nt = 0; nt < 8; ++nt) {
                        const float* bp = Es + (half * 64 + nt * 8 + g) * 68 + kc;
                        uint32_t bb[2] = {__float_as_uint(bp[0]), __float_as_uint(bp[4])};
                        mma16n8k8(qe[nt], a, bb);
                    }
                }
#pragma unroll
                for (int nt = 0; nt < 8; ++nt) {
                    const int col = half * 64 + nt * 8 + 2 * t;
                    *(__half2*)&dstT[(ms + g) * 136 + col] =
                        __floats2half2_rn(qe[nt][0], qe[nt][1]);
                    *(__half2*)&dstT[(ms + g + 8) * 136 + col] =
                        __floats2half2_rn(qe[nt][2], qe[nt][3]);
                }
            }
        }
        if (isA) {
            // QK into registers
#pragma unroll
            for (int nt = 0; nt < 8; ++nt)
#pragma unroll
                for (int r = 0; r < 4; ++r) S[nt][r] = 0.f;
#pragma unroll
            for (int ks = 0; ks < 8; ++ks) {
                const int kc = ks * 8 + t;
                uint32_t a[4];
                const float* ap = Qs + (ms + g) * 68 + kc;
                a[0] = __float_as_uint(ap[0]);
                a[1] = __float_as_uint(ap[8 * 68]);
                a[2] = __float_as_uint(ap[4]);
                a[3] = __float_as_uint(ap[8 * 68 + 4]);
#pragma unroll
                for (int nt = 0; nt < 8; ++nt) {
                    const float* bp = Ks + (nt * 8 + g) * 68 + kc;
                    uint32_t bb[2] = {__float_as_uint(bp[0]), __float_as_uint(bp[4])};
                    mma16n8k8(S[nt], a, bb);
                }
            }
        }
        __syncthreads();   // sync3: QEh/KEh complete; Ks reads done

        if (isA) {
            // ---- gather bias + scale + mask + online softmax ----
            const int iA = ms + g, iB = ms + g + 8;
            float rmax0 = -CUDART_INF_F, rmax1 = -CUDART_INF_F;
#pragma unroll
            for (int nt = 0; nt < 8; ++nt) {
                const int j0 = nt * 8 + 2 * t, j1 = j0 + 1;
                const float mk0 = maskS[j0], mk1 = maskS[j1];
                const int bA0 = iA - j0 + 63, bA1 = iA - j1 + 63;
                const int bB0 = iB - j0 + 63, bB1 = iB - j1 + 63;
                S[nt][0] = (S[nt][0] + __half2float(QEh[iA * 136 + bA0])
                                     + __half2float(KEh[j0 * 136 + bA0])) * 0.125f + mk0;
                S[nt][1] = (S[nt][1] + __half2float(QEh[iA * 136 + bA1])
                                     + __half2float(KEh[j1 * 136 + bA1])) * 0.125f + mk1;
                S[nt][2] = (S[nt][2] + __half2float(QEh[iB * 136 + bB0])
                                     + __half2float(KEh[j0 * 136 + bB0])) * 0.125f + mk0;
                S[nt][3] = (S[nt][3] + __half2float(QEh[iB * 136 + bB1])
                                     + __half2float(KEh[j1 * 136 + bB1])) * 0.125f + mk1;
                rmax0 = fmaxf(rmax0, fmaxf(S[nt][0], S[nt][1]));
                rmax1 = fmaxf(rmax1, fmaxf(S[nt][2], S[nt][3]));
            }
            rmax0 = fmaxf(rmax0, __shfl_xor_sync(0xffffffffu, rmax0, 1));
            rmax0 = fmaxf(rmax0, __shfl_xor_sync(0xffffffffu, rmax0, 2));
            rmax1 = fmaxf(rmax1, __shfl_xor_sync(0xffffffffu, rmax1, 1));
            rmax1 = fmaxf(rmax1, __shfl_xor_sync(0xffffffffu, rmax1, 2));
            const float mn0 = fmaxf(mrow0, rmax0), mn1 = fmaxf(mrow1, rmax1);
            const float c0 = __expf(mrow0 - mn0), c1 = __expf(mrow1 - mn1);
            mrow0 = mn0; mrow1 = mn1;
            float ps0 = 0.f, ps1 = 0.f;
#pragma unroll
            for (int nt = 0; nt < 8; ++nt) {
                S[nt][0] = __expf(S[nt][0] - mn0); ps0 += S[nt][0];
                S[nt][1] = __expf(S[nt][1] - mn0); ps0 += S[nt][1];
                S[nt][2] = __expf(S[nt][2] - mn1); ps1 += S[nt][2];
                S[nt][3] = __expf(S[nt][3] - mn1); ps1 += S[nt][3];
            }
            ps0 += __shfl_xor_sync(0xffffffffu, ps0, 1);
            ps0 += __shfl_xor_sync(0xffffffffu, ps0, 2);
            ps1 += __shfl_xor_sync(0xffffffffu, ps1, 1);
            ps1 += __shfl_xor_sync(0xffffffffu, ps1, 2);
            lsum0 = lsum0 * c0 + ps0;
            lsum1 = lsum1 * c1 + ps1;
            if (t == 0) { corrs[iA] = c0; corrs[iB] = c1; }
        } else {
            // ---- warps 4-7: stage V transposed (tf32) into Vt (alias Ks) ----
            const float* Vg = g_V + ((size_t)bh * SEQ + r0) * HD;
            const int tl = tid - 128;
#pragma unroll
            for (int it = 0; it < 8; ++it) {
                const int idx = tl * 4 + it * 512;
                const int j = idx >> 6, cc = idx & 63;
                float4 v = *(const float4*)(Vg + j * HD + cc);
                Vt[(cc + 0) * 68 + j] = tf32r(v.x);
                Vt[(cc + 1) * 68 + j] = tf32r(v.y);
                Vt[(cc + 2) * 68 + j] = tf32r(v.z);
                Vt[(cc + 3) * 68 + j] = tf32r(v.w);
            }
        }
        __syncthreads();   // sync4: gather done (QEh region free), corrs ready

        if (isA) {
            // ---- store P (tf32-rounded) into Ps (alias Es) ----
#pragma unroll
            for (int nt = 0; nt < 8; ++nt) {
                const int col = nt * 8 + 2 * t;
                *(float2*)&Ps[(ms + g) * 68 + col] =
                    make_float2(tf32r(S[nt][0]), tf32r(S[nt][1]));
                *(float2*)&Ps[(ms + g + 8) * 68 + col] =
                    make_float2(tf32r(S[nt][2]), tf32r(S[nt][3]));
            }
        }
        __syncthreads();   // sync5: Ps + Vt ready

        // ---- PV: all warps, strip ms x n-half nh ----
        {
            const float cc0 = corrs[ms + g], cc1 = corrs[ms + g + 8];
#pragma unroll
            for (int nt = 0; nt < 4; ++nt) {
                acc[nt][0] *= cc0; acc[nt][1] *= cc0;
                acc[nt][2] *= cc1; acc[nt][3] *= cc1;
            }
#pragma unroll
            for (int ks = 0; ks < 8; ++ks) {
                const int kc = ks * 8 + t;
                uint32_t a[4];
                const float* ap = Ps + (ms + g) * 68 + kc;
                a[0] = __float_as_uint(ap[0]);
                a[1] = __float_as_uint(ap[8 * 68]);
                a[2] = __float_as_uint(ap[4]);
                a[3] = __float_as_uint(ap[8 * 68 + 4]);
#pragma unroll
                for (int nt = 0; nt < 4; ++nt) {
                    const float* bp = Vt + (nh + nt * 8 + g) * 68 + kc;
                    uint32_t bb[2] = {__float_as_uint(bp[0]), __float_as_uint(bp[4])};
                    mma16n8k8(acc[nt], a, bb);
                }
            }
        }
    }

    if (isA && t == 0) { lsums[ms + g] = lsum0; lsums[ms + g + 8] = lsum1; }
    __syncthreads();

    {
        const float inv0 = 1.f / lsums[ms + g];
        const float inv1 = 1.f / lsums[ms + g + 8];
        const int row0 = l0 + ms + g, row1 = row0 + 8;
#pragma unroll
        for (int nt = 0; nt < 4; ++nt) {
            const int col = hh * HD + nh + nt * 8 + 2 * t;
            *(float2*)(out + (size_t)(b * SEQ + row0) * HID + col) =
                make_float2(acc[nt][0] * inv0, acc[nt][1] * inv0);
            *(float2*)(out + (size_t)(b * SEQ + row1) * HID + col) =
                make_float2(acc[nt][2] * inv1, acc[nt][3] * inv1);
        }
    }
}

// ---------------------------------------------------------------------------
extern "C" void kernel_launch(void* const* d_in, const int* in_sizes, int n_in,
                              void* d_out, int out_size)
{
    (void)in_sizes; (void)n_in; (void)out_size;
    const float* hs   = (const float*)d_in[0];
    const float* w    = (const float*)d_in[1];
    const float* bias = (const float*)d_in[2];
    const float* emb  = (const float*)d_in[3];
    const float* mask = (const float*)d_in[4];
    float* out = (float*)d_out;

    cudaFuncSetAttribute(qkv_gemm_mma,
                         cudaFuncAttributeMaxDynamicSharedMemorySize, QG_SMEM_B);
    qkv_gemm_mma<<<dim3(HID * 3 / 128, BATCH * SEQ / 128), 256, QG_SMEM_B>>>(hs, w, bias);

    cudaFuncSetAttribute(attn_mma,
                         cudaFuncAttributeMaxDynamicSharedMemorySize, AT_SMEM_B);
    attn_mma<<<dim3(SEQ / 64, BATCH * NH), 256, AT_SMEM_B>>>(emb, mask, out);
}

// round 9
// speedup vs baseline: 2.4944x; 1.4067x over previous
#include <cuda_runtime.h>
#include <cuda_fp16.h>
#include <math_constants.h>
#include <cstdint>

#define NH    16
#define HD    64
#define SEQ   1024
#define BATCH 4
#define HID   1024

// scratch: Q/K/V in [b, h, s, d] layout (16 MB each)
__device__ float g_Q[BATCH * NH * SEQ * HD];
__device__ float g_K[BATCH * NH * SEQ * HD];
__device__ float g_V[BATCH * NH * SEQ * HD];

__device__ __forceinline__ float tf32r(float x) {
    uint32_t u;
    asm("cvt.rna.tf32.f32 %0, %1;" : "=r"(u) : "f"(x));
    return __uint_as_float(u);
}
__device__ __forceinline__ uint32_t h2u(float x, float y) {
    __half2 h = __floats2half2_rn(x, y);
    return *(uint32_t*)&h;
}

__device__ __forceinline__ void mma16n8k8(float c[4], const uint32_t a[4],
                                          const uint32_t b[2]) {
    asm volatile(
        "mma.sync.aligned.m16n8k8.row.col.f32.tf32.tf32.f32 "
        "{%0,%1,%2,%3}, {%4,%5,%6,%7}, {%8,%9}, {%0,%1,%2,%3};"
        : "+f"(c[0]), "+f"(c[1]), "+f"(c[2]), "+f"(c[3])
        : "r"(a[0]), "r"(a[1]), "r"(a[2]), "r"(a[3]), "r"(b[0]), "r"(b[1]));
}
__device__ __forceinline__ void mma16n8k16h(float c[4], const uint32_t a[4],
                                            const uint32_t b[2]) {
    asm volatile(
        "mma.sync.aligned.m16n8k16.row.col.f32.f16.f16.f32 "
        "{%0,%1,%2,%3}, {%4,%5,%6,%7}, {%8,%9}, {%0,%1,%2,%3};"
        : "+f"(c[0]), "+f"(c[1]), "+f"(c[2]), "+f"(c[3])
        : "r"(a[0]), "r"(a[1]), "r"(a[2]), "r"(a[3]), "r"(b[0]), "r"(b[1]));
}

// ===========================================================================
// Kernel 1: fused QKV projection via mma.sync fp16 (same 10-bit mantissa as
// tf32, 2x k per mma, half the smem traffic).  Block 128x128, BK=32, 8 warps.
// ===========================================================================
#define SSTH 40                       // halves per row (32 + pad)
#define QH_TILE (128 * SSTH)          // halves per tile buffer
#define QG_SMEM_B (4 * QH_TILE * 2)   // A0/A1/B0/B1

__global__ __launch_bounds__(256) void qkv_gemm_mma(
    const float* __restrict__ hs,
    const float* __restrict__ w,
    const float* __restrict__ bias)
{
    extern __shared__ __align__(16) __half smh[];
    __half* As = smh;                 // [2][128][40]
    __half* Bs = smh + 2 * QH_TILE;

    const int tid  = threadIdx.x;
    const int m0   = blockIdx.y * 128;
    const int n0   = blockIdx.x * 128;
    const int lrow = tid >> 3;
    const int lc4  = tid & 7;

    const int lane = tid & 31, g = lane >> 2, t = lane & 3;
    const int wid  = tid >> 5, wm = wid >> 2, wn = wid & 3;

    float4 ra[4], rb[4];

#pragma unroll
    for (int it = 0; it < 4; ++it) {
        const int row = lrow + it * 32;
        ra[it] = *(const float4*)(hs + (size_t)(m0 + row) * HID + lc4 * 4);
        rb[it] = *(const float4*)(w  + (size_t)(n0 + row) * HID + lc4 * 4);
    }
#pragma unroll
    for (int it = 0; it < 4; ++it) {
        const int row = lrow + it * 32;
        *(uint2*)&As[row * SSTH + lc4 * 4] =
            make_uint2(h2u(ra[it].x, ra[it].y), h2u(ra[it].z, ra[it].w));
        *(uint2*)&Bs[row * SSTH + lc4 * 4] =
            make_uint2(h2u(rb[it].x, rb[it].y), h2u(rb[it].z, rb[it].w));
    }
    __syncthreads();

    float c[4][4][4];
#pragma unroll
    for (int mi = 0; mi < 4; ++mi)
#pragma unroll
        for (int ni = 0; ni < 4; ++ni)
#pragma unroll
            for (int r = 0; r < 4; ++r) c[mi][ni][r] = 0.f;

    for (int ch = 0; ch < 32; ++ch) {
        const int p = ch & 1;
        if (ch < 31) {
            const int k0 = (ch + 1) * 32;
#pragma unroll
            for (int it = 0; it < 4; ++it) {
                const int row = lrow + it * 32;
                ra[it] = *(const float4*)(hs + (size_t)(m0 + row) * HID + k0 + lc4 * 4);
                rb[it] = *(const float4*)(w  + (size_t)(n0 + row) * HID + k0 + lc4 * 4);
            }
        }

        const __half* Ab = As + p * QH_TILE;
        const __half* Bb = Bs + p * QH_TILE;
#pragma unroll
        for (int ks = 0; ks < 2; ++ks) {
            const int kc = ks * 16 + 2 * t;
            uint32_t a[4][4], b[4][2];
#pragma unroll
            for (int mi = 0; mi < 4; ++mi) {
                const __half* ap = Ab + (wm * 64 + mi * 16 + g) * SSTH + kc;
                a[mi][0] = *(const uint32_t*)(ap);
                a[mi][1] = *(const uint32_t*)(ap + 8 * SSTH);
                a[mi][2] = *(const uint32_t*)(ap + 8);
                a[mi][3] = *(const uint32_t*)(ap + 8 * SSTH + 8);
            }
#pragma unroll
            for (int ni = 0; ni < 4; ++ni) {
                const __half* bp = Bb + (wn * 32 + ni * 8 + g) * SSTH + kc;
                b[ni][0] = *(const uint32_t*)(bp);
                b[ni][1] = *(const uint32_t*)(bp + 8);
            }
#pragma unroll
            for (int mi = 0; mi < 4; ++mi)
#pragma unroll
                for (int ni = 0; ni < 4; ++ni)
                    mma16n8k16h(c[mi][ni], a[mi], b[ni]);
        }

        if (ch < 31) {
            __half* An = As + ((ch + 1) & 1) * QH_TILE;
            __half* Bn = Bs + ((ch + 1) & 1) * QH_TILE;
#pragma unroll
            for (int it = 0; it < 4; ++it) {
                const int row = lrow + it * 32;
                *(uint2*)&An[row * SSTH + lc4 * 4] =
                    make_uint2(h2u(ra[it].x, ra[it].y), h2u(ra[it].z, ra[it].w));
                *(uint2*)&Bn[row * SSTH + lc4 * 4] =
                    make_uint2(h2u(rb[it].x, rb[it].y), h2u(rb[it].z, rb[it].w));
            }
        }
        __syncthreads();
    }

    const int tsel = n0 >> 10;
    float* dst = (tsel == 0) ? g_Q : (tsel == 1) ? g_K : g_V;
#pragma unroll
    for (int mi = 0; mi < 4; ++mi) {
        const int m  = m0 + wm * 64 + mi * 16 + g;
        const int bb = m >> 10;
        const int s  = m & 1023;
#pragma unroll
        for (int ni = 0; ni < 4; ++ni) {
            const int gn  = n0 + wn * 32 + ni * 8 + t * 2;
            const int rem = gn & 1023;
            const int hh  = rem >> 6;
            const int dd  = rem & 63;
            const float2 bi = *(const float2*)(bias + gn);
            float* base = dst + ((size_t)(bb * NH + hh) * SEQ + s) * HD + dd;
            *(float2*)(base) = make_float2(c[mi][ni][0] + bi.x, c[mi][ni][1] + bi.y);
            *(float2*)(base + 8 * HD) = make_float2(c[mi][ni][2] + bi.x, c[mi][ni][3] + bi.y);
        }
    }
}

// ===========================================================================
// Kernel 2: attention on mma.sync.  QK/PV in tf32; QE/KE in fp16 m16n8k16,
// band-trimmed to the 80-col diagonal strip actually gathered.
// Warps 0-3 (A): QE+QK+softmax+P.  Warps 4-7 (B): KE + Vt staging.  All: PV.
// ===========================================================================
#define AT_SMEM_B 107264

__global__ __launch_bounds__(256, 2) void attn_mma(
    const float* __restrict__ emb,
    const float* __restrict__ mask,
    float* __restrict__ out)
{
    extern __shared__ __align__(16) float sm2[];
    float*  Qs    = sm2;                      // [64][68] f32 (tf32)
    float*  Ks    = sm2 + 4352;               // [64][68] f32 (Vt alias)
    float*  Vt    = Ks;
    __half* Eh    = (__half*)(sm2 + 8704);    // [128][72] f16 (Ps alias)
    float*  Ps    = sm2 + 8704;               // [64][68] f32
    __half* Qh    = (__half*)(sm2 + 13312);   // [64][72] f16
    __half* Kh    = (__half*)(sm2 + 15616);   // [64][72] f16
    __half* QEh   = (__half*)(sm2 + 17920);   // [64][136] f16
    __half* KEh   = (__half*)(sm2 + 22272);   // [64][136] f16
    float*  corrs = sm2 + 26624;              // [64]
    float*  lsums = sm2 + 26688;              // [64]
    float*  maskS = sm2 + 26752;              // [64]

    const int tid  = threadIdx.x;
    const int lane = tid & 31, g = lane >> 2, t = lane & 3;
    const int wid  = tid >> 5;
    const int ms   = (wid & 3) * 16;          // 16-row strip
    const int nh   = (wid >> 2) * 32;         // n-half for PV
    const bool isA = (wid < 4);
    const int bh = blockIdx.y, b = bh >> 4, hh = bh & 15;
    const int l0 = blockIdx.x * 64;

    // ---- stage Q (tf32 f32 + fp16) ----
    const float* Qg = g_Q + ((size_t)bh * SEQ + l0) * HD;
#pragma unroll
    for (int it = 0; it < 4; ++it) {
        const int idx = tid * 4 + it * 1024;
        const int i = idx >> 6, dd = idx & 63;
        float4 v = *(const float4*)(Qg + idx);
        *(float4*)&Qs[i * 68 + dd] =
            make_float4(tf32r(v.x), tf32r(v.y), tf32r(v.z), tf32r(v.w));
        *(uint2*)&Qh[i * 72 + dd] = make_uint2(h2u(v.x, v.y), h2u(v.z, v.w));
    }

    float mrow0 = -CUDART_INF_F, mrow1 = -CUDART_INF_F;
    float lsum0 = 0.f, lsum1 = 0.f;
    float acc[4][4];
#pragma unroll
    for (int nt = 0; nt < 4; ++nt)
#pragma unroll
        for (int r = 0; r < 4; ++r) acc[nt][r] = 0.f;

    float S[8][4];
    const int ebase = isA ? ms : (48 - ms);   // band start col for QE / KE

    for (int r0 = 0; r0 < SEQ; r0 += 64) {
        const int gb_ = l0 - r0 + 960;

        __syncthreads();   // sync1: prior PV reads (Ps, Vt) done
        // ---- stage K (f32+f16), E band (f16), mask ----
        const float* Kg = g_K + ((size_t)bh * SEQ + r0) * HD;
#pragma unroll
        for (int it = 0; it < 4; ++it) {
            const int idx = tid * 4 + it * 1024;
            const int i = idx >> 6, dd = idx & 63;
            float4 v = *(const float4*)(Kg + idx);
            *(float4*)&Ks[i * 68 + dd] =
                make_float4(tf32r(v.x), tf32r(v.y), tf32r(v.z), tf32r(v.w));
            *(uint2*)&Kh[i * 72 + dd] = make_uint2(h2u(v.x, v.y), h2u(v.z, v.w));
        }
#pragma unroll
        for (int it = 0; it < 8; ++it) {
            const int idx = tid * 4 + it * 1024;
            const int r = idx >> 6, dd = idx & 63;
            const int er = min(gb_ + r, 2046);
            float4 v = *(const float4*)(emb + (size_t)er * HD + dd);
            *(uint2*)&Eh[r * 72 + dd] = make_uint2(h2u(v.x, v.y), h2u(v.z, v.w));
        }
        if (tid < 16)
            *(float4*)&maskS[tid * 4] = *(const float4*)(mask + b * SEQ + r0 + tid * 4);
        __syncthreads();   // sync2: operands ready

        // ---- fp16 band GEMM: QE (A warps) / KE (B warps), 10 n8 tiles ----
        {
            const __half* Ah = isA ? Qh : Kh;
            __half* dstT = isA ? QEh : KEh;
#pragma unroll
            for (int c5 = 0; c5 < 2; ++c5) {
                float qe[5][4];
#pragma unroll
                for (int nt = 0; nt < 5; ++nt)
#pragma unroll
                    for (int r = 0; r < 4; ++r) qe[nt][r] = 0.f;
#pragma unroll
                for (int ks = 0; ks < 4; ++ks) {
                    const int kc = ks * 16 + 2 * t;
                    uint32_t a[4];
                    const __half* ap = Ah + (ms + g) * 72 + kc;
                    a[0] = *(const uint32_t*)(ap);
                    a[1] = *(const uint32_t*)(ap + 8 * 72);
                    a[2] = *(const uint32_t*)(ap + 8);
                    a[3] = *(const uint32_t*)(ap + 8 * 72 + 8);
#pragma unroll
                    for (int nt = 0; nt < 5; ++nt) {
                        const int col = ebase + (c5 * 5 + nt) * 8;
                        const __half* bp = Eh + (col + g) * 72 + kc;
                        uint32_t bb[2] = {*(const uint32_t*)(bp),
                                          *(const uint32_t*)(bp + 8)};
                        mma16n8k16h(qe[nt], a, bb);
                    }
                }
#pragma unroll
                for (int nt = 0; nt < 5; ++nt) {
                    const int col = ebase + (c5 * 5 + nt) * 8 + 2 * t;
                    *(__half2*)&dstT[(ms + g) * 136 + col] =
                        __floats2half2_rn(qe[nt][0], qe[nt][1]);
                    *(__half2*)&dstT[(ms + g + 8) * 136 + col] =
                        __floats2half2_rn(qe[nt][2], qe[nt][3]);
                }
            }
        }
        if (isA) {
            // ---- QK (tf32) ----
#pragma unroll
            for (int nt = 0; nt < 8; ++nt)
#pragma unroll
                for (int r = 0; r < 4; ++r) S[nt][r] = 0.f;
#pragma unroll
            for (int ks = 0; ks < 8; ++ks) {
                const int kc = ks * 8 + t;
                uint32_t a[4];
                const float* ap = Qs + (ms + g) * 68 + kc;
                a[0] = __float_as_uint(ap[0]);
                a[1] = __float_as_uint(ap[8 * 68]);
                a[2] = __float_as_uint(ap[4]);
                a[3] = __float_as_uint(ap[8 * 68 + 4]);
#pragma unroll
                for (int nt = 0; nt < 8; ++nt) {
                    const float* bp = Ks + (nt * 8 + g) * 68 + kc;
                    uint32_t bb[2] = {__float_as_uint(bp[0]), __float_as_uint(bp[4])};
                    mma16n8k8(S[nt], a, bb);
                }
            }
        }
        __syncthreads();   // sync3: QEh/KEh done; Ks/Eh reads done

        if (isA) {
            // ---- gather + scale + mask + online softmax + P store ----
            const int iA = ms + g, iB = ms + g + 8;
            float rmax0 = -CUDART_INF_F, rmax1 = -CUDART_INF_F;
#pragma unroll
            for (int nt = 0; nt < 8; ++nt) {
                const int j0 = nt * 8 + 2 * t, j1 = j0 + 1;
                const float mk0 = maskS[j0], mk1 = maskS[j1];
                const int bA0 = iA - j0 + 63, bA1 = iA - j1 + 63;
                const int bB0 = iB - j0 + 63, bB1 = iB - j1 + 63;
                S[nt][0] = (S[nt][0] + __half2float(QEh[iA * 136 + bA0])
                                     + __half2float(KEh[j0 * 136 + bA0])) * 0.125f + mk0;
                S[nt][1] = (S[nt][1] + __half2float(QEh[iA * 136 + bA1])
                                     + __half2float(KEh[j1 * 136 + bA1])) * 0.125f + mk1;
                S[nt][2] = (S[nt][2] + __half2float(QEh[iB * 136 + bB0])
                                     + __half2float(KEh[j0 * 136 + bB0])) * 0.125f + mk0;
                S[nt][3] = (S[nt][3] + __half2float(QEh[iB * 136 + bB1])
                                     + __half2float(KEh[j1 * 136 + bB1])) * 0.125f + mk1;
                rmax0 = fmaxf(rmax0, fmaxf(S[nt][0], S[nt][1]));
                rmax1 = fmaxf(rmax1, fmaxf(S[nt][2], S[nt][3]));
            }
            rmax0 = fmaxf(rmax0, __shfl_xor_sync(0xffffffffu, rmax0, 1));
            rmax0 = fmaxf(rmax0, __shfl_xor_sync(0xffffffffu, rmax0, 2));
            rmax1 = fmaxf(rmax1, __shfl_xor_sync(0xffffffffu, rmax1, 1));
            rmax1 = fmaxf(rmax1, __shfl_xor_sync(0xffffffffu, rmax1, 2));
            const float mn0 = fmaxf(mrow0, rmax0), mn1 = fmaxf(mrow1, rmax1);
            const float c0 = __expf(mrow0 - mn0), c1 = __expf(mrow1 - mn1);
            mrow0 = mn0; mrow1 = mn1;
            float ps0 = 0.f, ps1 = 0.f;
#pragma unroll
            for (int nt = 0; nt < 8; ++nt) {
                S[nt][0] = __expf(S[nt][0] - mn0); ps0 += S[nt][0];
                S[nt][1] = __expf(S[nt][1] - mn0); ps0 += S[nt][1];
                S[nt][2] = __expf(S[nt][2] - mn1); ps1 += S[nt][2];
                S[nt][3] = __expf(S[nt][3] - mn1); ps1 += S[nt][3];
            }
            ps0 += __shfl_xor_sync(0xffffffffu, ps0, 1);
            ps0 += __shfl_xor_sync(0xffffffffu, ps0, 2);
            ps1 += __shfl_xor_sync(0xffffffffu, ps1, 1);
            ps1 += __shfl_xor_sync(0xffffffffu, ps1, 2);
            lsum0 = lsum0 * c0 + ps0;
            lsum1 = lsum1 * c1 + ps1;
            if (t == 0) { corrs[iA] = c0; corrs[iB] = c1; }
            // P store (tf32) into Ps (alias Eh, dead after sync3)
#pragma unroll
            for (int nt = 0; nt < 8; ++nt) {
                const int col = nt * 8 + 2 * t;
                *(float2*)&Ps[iA * 68 + col] =
                    make_float2(tf32r(S[nt][0]), tf32r(S[nt][1]));
                *(float2*)&Ps[iB * 68 + col] =
                    make_float2(tf32r(S[nt][2]), tf32r(S[nt][3]));
            }
        } else {
            // ---- B warps: stage V transposed (tf32) into Vt (alias Ks) ----
            const float* Vg = g_V + ((size_t)bh * SEQ + r0) * HD;
            const int tl = tid - 128;
#pragma unroll
            for (int it = 0; it < 8; ++it) {
                const int idx = tl * 4 + it * 512;
                const int j = idx >> 6, cc = idx & 63;
                float4 v = *(const float4*)(Vg + j * HD + cc);
                Vt[(cc + 0) * 68 + j] = tf32r(v.x);
                Vt[(cc + 1) * 68 + j] = tf32r(v.y);
                Vt[(cc + 2) * 68 + j] = tf32r(v.z);
                Vt[(cc + 3) * 68 + j] = tf32r(v.w);
            }
        }
        __syncthreads();   // sync4: Ps, Vt, corrs ready

        // ---- PV (tf32): all warps, strip ms x n-half nh ----
        {
            const float cc0 = corrs[ms + g], cc1 = corrs[ms + g + 8];
#pragma unroll
            for (int nt = 0; nt < 4; ++nt) {
                acc[nt][0] *= cc0; acc[nt][1] *= cc0;
                acc[nt][2] *= cc1; acc[nt][3] *= cc1;
            }
#pragma unroll
            for (int ks = 0; ks < 8; ++ks) {
                const int kc = ks * 8 + t;
                uint32_t a[4];
                const float* ap = Ps + (ms + g) * 68 + kc;
                a[0] = __float_as_uint(ap[0]);
                a[1] = __float_as_uint(ap[8 * 68]);
                a[2] = __float_as_uint(ap[4]);
                a[3] = __float_as_uint(ap[8 * 68 + 4]);
#pragma unroll
                for (int nt = 0; nt < 4; ++nt) {
                    const float* bp = Vt + (nh + nt * 8 + g) * 68 + kc;
                    uint32_t bb[2] = {__float_as_uint(bp[0]), __float_as_uint(bp[4])};
                    mma16n8k8(acc[nt], a, bb);
                }
            }
        }
    }

    if (isA && t == 0) { lsums[ms + g] = lsum0; lsums[ms + g + 8] = lsum1; }
    __syncthreads();

    {
        const float inv0 = 1.f / lsums[ms + g];
        const float inv1 = 1.f / lsums[ms + g + 8];
        const int row0 = l0 + ms + g, row1 = row0 + 8;
#pragma unroll
        for (int nt = 0; nt < 4; ++nt) {
            const int col = hh * HD + nh + nt * 8 + 2 * t;
            *(float2*)(out + (size_t)(b * SEQ + row0) * HID + col) =
                make_float2(acc[nt][0] * inv0, acc[nt][1] * inv0);
            *(float2*)(out + (size_t)(b * SEQ + row1) * HID + col) =
                make_float2(acc[nt][2] * inv1, acc[nt][3] * inv1);
        }
    }
}

// ---------------------------------------------------------------------------
extern "C" void kernel_launch(void* const* d_in, const int* in_sizes, int n_in,
                              void* d_out, int out_size)
{
    (void)in_sizes; (void)n_in; (void)out_size;
    const float* hs   = (const float*)d_in[0];
    const float* w    = (const float*)d_in[1];
    const float* bias = (const float*)d_in[2];
    const float* emb  = (const float*)d_in[3];
    const float* mask = (const float*)d_in[4];
    float* out = (float*)d_out;

    cudaFuncSetAttribute(qkv_gemm_mma,
                         cudaFuncAttributeMaxDynamicSharedMemorySize, QG_SMEM_B);
    qkv_gemm_mma<<<dim3(HID * 3 / 128, BATCH * SEQ / 128), 256, QG_SMEM_B>>>(hs, w, bias);

    cudaFuncSetAttribute(attn_mma,
                         cudaFuncAttributeMaxDynamicSharedMemorySize, AT_SMEM_B);
    attn_mma<<<dim3(SEQ / 64, BATCH * NH), 256, AT_SMEM_B>>>(emb, mask, out);
}

// round 10
// speedup vs baseline: 3.1546x; 1.2647x over previous
#include <cuda_runtime.h>
#include <cuda_fp16.h>
#include <math_constants.h>
#include <cstdint>

#define NH    16
#define HD    64
#define SEQ   1024
#define BATCH 4
#define HID   1024

// scratch: Q/K/V in [b, h, s, d] layout (16 MB each)
__device__ float g_Q[BATCH * NH * SEQ * HD];
__device__ float g_K[BATCH * NH * SEQ * HD];
__device__ float g_V[BATCH * NH * SEQ * HD];

__device__ __forceinline__ uint32_t h2u(float x, float y) {
    __half2 h = __floats2half2_rn(x, y);
    return *(uint32_t*)&h;
}

__device__ __forceinline__ void mma16n8k16h(float c[4], const uint32_t a[4],
                                            const uint32_t b[2]) {
    asm volatile(
        "mma.sync.aligned.m16n8k16.row.col.f32.f16.f16.f32 "
        "{%0,%1,%2,%3}, {%4,%5,%6,%7}, {%8,%9}, {%0,%1,%2,%3};"
        : "+f"(c[0]), "+f"(c[1]), "+f"(c[2]), "+f"(c[3])
        : "r"(a[0]), "r"(a[1]), "r"(a[2]), "r"(a[3]), "r"(b[0]), "r"(b[1]));
}

// ===========================================================================
// Kernel 1: fused QKV projection via mma.sync fp16 (unchanged — WIN from R9)
// ===========================================================================
#define SSTH 40
#define QH_TILE (128 * SSTH)
#define QG_SMEM_B (4 * QH_TILE * 2)

__global__ __launch_bounds__(256) void qkv_gemm_mma(
    const float* __restrict__ hs,
    const float* __restrict__ w,
    const float* __restrict__ bias)
{
    extern __shared__ __align__(16) __half smh[];
    __half* As = smh;
    __half* Bs = smh + 2 * QH_TILE;

    const int tid  = threadIdx.x;
    const int m0   = blockIdx.y * 128;
    const int n0   = blockIdx.x * 128;
    const int lrow = tid >> 3;
    const int lc4  = tid & 7;

    const int lane = tid & 31, g = lane >> 2, t = lane & 3;
    const int wid  = tid >> 5, wm = wid >> 2, wn = wid & 3;

    float4 ra[4], rb[4];

#pragma unroll
    for (int it = 0; it < 4; ++it) {
        const int row = lrow + it * 32;
        ra[it] = *(const float4*)(hs + (size_t)(m0 + row) * HID + lc4 * 4);
        rb[it] = *(const float4*)(w  + (size_t)(n0 + row) * HID + lc4 * 4);
    }
#pragma unroll
    for (int it = 0; it < 4; ++it) {
        const int row = lrow + it * 32;
        *(uint2*)&As[row * SSTH + lc4 * 4] =
            make_uint2(h2u(ra[it].x, ra[it].y), h2u(ra[it].z, ra[it].w));
        *(uint2*)&Bs[row * SSTH + lc4 * 4] =
            make_uint2(h2u(rb[it].x, rb[it].y), h2u(rb[it].z, rb[it].w));
    }
    __syncthreads();

    float c[4][4][4];
#pragma unroll
    for (int mi = 0; mi < 4; ++mi)
#pragma unroll
        for (int ni = 0; ni < 4; ++ni)
#pragma unroll
            for (int r = 0; r < 4; ++r) c[mi][ni][r] = 0.f;

    for (int ch = 0; ch < 32; ++ch) {
        const int p = ch & 1;
        if (ch < 31) {
            const int k0 = (ch + 1) * 32;
#pragma unroll
            for (int it = 0; it < 4; ++it) {
                const int row = lrow + it * 32;
                ra[it] = *(const float4*)(hs + (size_t)(m0 + row) * HID + k0 + lc4 * 4);
                rb[it] = *(const float4*)(w  + (size_t)(n0 + row) * HID + k0 + lc4 * 4);
            }
        }

        const __half* Ab = As + p * QH_TILE;
        const __half* Bb = Bs + p * QH_TILE;
#pragma unroll
        for (int ks = 0; ks < 2; ++ks) {
            const int kc = ks * 16 + 2 * t;
            uint32_t a[4][4], b[4][2];
#pragma unroll
            for (int mi = 0; mi < 4; ++mi) {
                const __half* ap = Ab + (wm * 64 + mi * 16 + g) * SSTH + kc;
                a[mi][0] = *(const uint32_t*)(ap);
                a[mi][1] = *(const uint32_t*)(ap + 8 * SSTH);
                a[mi][2] = *(const uint32_t*)(ap + 8);
                a[mi][3] = *(const uint32_t*)(ap + 8 * SSTH + 8);
            }
#pragma unroll
            for (int ni = 0; ni < 4; ++ni) {
                const __half* bp = Bb + (wn * 32 + ni * 8 + g) * SSTH + kc;
                b[ni][0] = *(const uint32_t*)(bp);
                b[ni][1] = *(const uint32_t*)(bp + 8);
            }
#pragma unroll
            for (int mi = 0; mi < 4; ++mi)
#pragma unroll
                for (int ni = 0; ni < 4; ++ni)
                    mma16n8k16h(c[mi][ni], a[mi], b[ni]);
        }

        if (ch < 31) {
            __half* An = As + ((ch + 1) & 1) * QH_TILE;
            __half* Bn = Bs + ((ch + 1) & 1) * QH_TILE;
#pragma unroll
            for (int it = 0; it < 4; ++it) {
                const int row = lrow + it * 32;
                *(uint2*)&An[row * SSTH + lc4 * 4] =
                    make_uint2(h2u(ra[it].x, ra[it].y), h2u(ra[it].z, ra[it].w));
                *(uint2*)&Bn[row * SSTH + lc4 * 4] =
                    make_uint2(h2u(rb[it].x, rb[it].y), h2u(rb[it].z, rb[it].w));
            }
        }
        __syncthreads();
    }

    const int tsel = n0 >> 10;
    float* dst = (tsel == 0) ? g_Q : (tsel == 1) ? g_K : g_V;
#pragma unroll
    for (int mi = 0; mi < 4; ++mi) {
        const int m  = m0 + wm * 64 + mi * 16 + g;
        const int bb = m >> 10;
        const int s  = m & 1023;
#pragma unroll
        for (int ni = 0; ni < 4; ++ni) {
            const int gn  = n0 + wn * 32 + ni * 8 + t * 2;
            const int rem = gn & 1023;
            const int hh  = rem >> 6;
            const int dd  = rem & 63;
            const float2 bi = *(const float2*)(bias + gn);
            float* base = dst + ((size_t)(bb * NH + hh) * SEQ + s) * HD + dd;
            *(float2*)(base) = make_float2(c[mi][ni][0] + bi.x, c[mi][ni][1] + bi.y);
            *(float2*)(base + 8 * HD) = make_float2(c[mi][ni][2] + bi.x, c[mi][ni][3] + bi.y);
        }
    }
}

// ===========================================================================
// Kernel 2: attention, ALL GEMMs fp16 m16n8k16 (fp16 mantissa == tf32).
// Warps 0-3 (A): QE + QK + softmax + P.  Warps 4-7 (B): KE + Vt staging.
// All warps: PV.  smem 72448 B -> 2 blocks/SM.
// ===========================================================================
#define AT_SMEM_B 72448

__global__ __launch_bounds__(256, 2) void attn_mma(
    const float* __restrict__ emb,
    const float* __restrict__ mask,
    float* __restrict__ out)
{
    extern __shared__ __align__(16) float sm2[];
    __half* Qh    = (__half*)sm2;             // [64][72]
    __half* Kh    = (__half*)(sm2 + 2304);    // [64][72] (Vth alias, stride 68)
    __half* Vth   = Kh;
    __half* Eh    = (__half*)(sm2 + 4608);    // [128][72] (Ph alias [64][72])
    __half* Ph    = Eh;
    __half* QEh   = (__half*)(sm2 + 9216);    // [64][136]
    __half* KEh   = (__half*)(sm2 + 13568);   // [64][136]
    float*  corrs = sm2 + 17920;              // [64]
    float*  lsums = sm2 + 17984;              // [64]
    float*  maskS = sm2 + 18048;              // [64]

    const int tid  = threadIdx.x;
    const int lane = tid & 31, g = lane >> 2, t = lane & 3;
    const int wid  = tid >> 5;
    const int ms   = (wid & 3) * 16;          // 16-row strip
    const int nh   = (wid >> 2) * 32;         // n-half for PV
    const bool isA = (wid < 4);
    const int bh = blockIdx.y, b = bh >> 4, hh = bh & 15;
    const int l0 = blockIdx.x * 64;

    // ---- stage Q (fp16) ----
    const float* Qg = g_Q + ((size_t)bh * SEQ + l0) * HD;
#pragma unroll
    for (int it = 0; it < 4; ++it) {
        const int idx = tid * 4 + it * 1024;
        const int i = idx >> 6, dd = idx & 63;
        float4 v = *(const float4*)(Qg + idx);
        *(uint2*)&Qh[i * 72 + dd] = make_uint2(h2u(v.x, v.y), h2u(v.z, v.w));
    }

    float mrow0 = -CUDART_INF_F, mrow1 = -CUDART_INF_F;
    float lsum0 = 0.f, lsum1 = 0.f;
    float acc[4][4];
#pragma unroll
    for (int nt = 0; nt < 4; ++nt)
#pragma unroll
        for (int r = 0; r < 4; ++r) acc[nt][r] = 0.f;

    float S[8][4];
    const int ebase = isA ? ms : (48 - ms);   // band start col for QE / KE

    for (int r0 = 0; r0 < SEQ; r0 += 64) {
        const int gb_ = l0 - r0 + 960;

        __syncthreads();   // sync1: prior PV reads (Ph, Vth) done
        // ---- stage K (fp16), E band (fp16), mask ----
        const float* Kg = g_K + ((size_t)bh * SEQ + r0) * HD;
#pragma unroll
        for (int it = 0; it < 4; ++it) {
            const int idx = tid * 4 + it * 1024;
            const int i = idx >> 6, dd = idx & 63;
            float4 v = *(const float4*)(Kg + idx);
            *(uint2*)&Kh[i * 72 + dd] = make_uint2(h2u(v.x, v.y), h2u(v.z, v.w));
        }
#pragma unroll
        for (int it = 0; it < 8; ++it) {
            const int idx = tid * 4 + it * 1024;
            const int r = idx >> 6, dd = idx & 63;
            const int er = min(gb_ + r, 2046);
            float4 v = *(const float4*)(emb + (size_t)er * HD + dd);
            *(uint2*)&Eh[r * 72 + dd] = make_uint2(h2u(v.x, v.y), h2u(v.z, v.w));
        }
        if (tid < 16)
            *(float4*)&maskS[tid * 4] = *(const float4*)(mask + b * SEQ + r0 + tid * 4);
        __syncthreads();   // sync2: operands ready

        // ---- fp16 band GEMM: QE (A warps) / KE (B warps), 10 n8 tiles ----
        {
            const __half* Ah = isA ? Qh : Kh;
            __half* dstT = isA ? QEh : KEh;
#pragma unroll
            for (int c5 = 0; c5 < 2; ++c5) {
                float qe[5][4];
#pragma unroll
                for (int nt = 0; nt < 5; ++nt)
#pragma unroll
                    for (int r = 0; r < 4; ++r) qe[nt][r] = 0.f;
#pragma unroll
                for (int ks = 0; ks < 4; ++ks) {
                    const int kc = ks * 16 + 2 * t;
                    uint32_t a[4];
                    const __half* ap = Ah + (ms + g) * 72 + kc;
                    a[0] = *(const uint32_t*)(ap);
                    a[1] = *(const uint32_t*)(ap + 8 * 72);
                    a[2] = *(const uint32_t*)(ap + 8);
                    a[3] = *(const uint32_t*)(ap + 8 * 72 + 8);
#pragma unroll
                    for (int nt = 0; nt < 5; ++nt) {
                        const int col = ebase + (c5 * 5 + nt) * 8;
                        const __half* bp = Eh + (col + g) * 72 + kc;
                        uint32_t bb[2] = {*(const uint32_t*)(bp),
                                          *(const uint32_t*)(bp + 8)};
                        mma16n8k16h(qe[nt], a, bb);
                    }
                }
#pragma unroll
                for (int nt = 0; nt < 5; ++nt) {
                    const int col = ebase + (c5 * 5 + nt) * 8 + 2 * t;
                    *(__half2*)&dstT[(ms + g) * 136 + col] =
                        __floats2half2_rn(qe[nt][0], qe[nt][1]);
                    *(__half2*)&dstT[(ms + g + 8) * 136 + col] =
                        __floats2half2_rn(qe[nt][2], qe[nt][3]);
                }
            }
        }
        if (isA) {
            // ---- QK (fp16, k=16) ----
#pragma unroll
            for (int nt = 0; nt < 8; ++nt)
#pragma unroll
                for (int r = 0; r < 4; ++r) S[nt][r] = 0.f;
#pragma unroll
            for (int ks = 0; ks < 4; ++ks) {
                const int kc = ks * 16 + 2 * t;
                uint32_t a[4];
                const __half* ap = Qh + (ms + g) * 72 + kc;
                a[0] = *(const uint32_t*)(ap);
                a[1] = *(const uint32_t*)(ap + 8 * 72);
                a[2] = *(const uint32_t*)(ap + 8);
                a[3] = *(const uint32_t*)(ap + 8 * 72 + 8);
#pragma unroll
                for (int nt = 0; nt < 8; ++nt) {
                    const __half* bp = Kh + (nt * 8 + g) * 72 + kc;
                    uint32_t bb[2] = {*(const uint32_t*)(bp),
                                      *(const uint32_t*)(bp + 8)};
                    mma16n8k16h(S[nt], a, bb);
                }
            }
        }
        __syncthreads();   // sync3: QEh/KEh done; Kh/Eh mma reads done

        if (isA) {
            // ---- gather + scale + mask + online softmax + P store (fp16) ----
            const int iA = ms + g, iB = ms + g + 8;
            float rmax0 = -CUDART_INF_F, rmax1 = -CUDART_INF_F;
#pragma unroll
            for (int nt = 0; nt < 8; ++nt) {
                const int j0 = nt * 8 + 2 * t, j1 = j0 + 1;
                const float mk0 = maskS[j0], mk1 = maskS[j1];
                const int bA0 = iA - j0 + 63, bA1 = iA - j1 + 63;
                const int bB0 = iB - j0 + 63, bB1 = iB - j1 + 63;
                S[nt][0] = (S[nt][0] + __half2float(QEh[iA * 136 + bA0])
                                     + __half2float(KEh[j0 * 136 + bA0])) * 0.125f + mk0;
                S[nt][1] = (S[nt][1] + __half2float(QEh[iA * 136 + bA1])
                                     + __half2float(KEh[j1 * 136 + bA1])) * 0.125f + mk1;
                S[nt][2] = (S[nt][2] + __half2float(QEh[iB * 136 + bB0])
                                     + __half2float(KEh[j0 * 136 + bB0])) * 0.125f + mk0;
                S[nt][3] = (S[nt][3] + __half2float(QEh[iB * 136 + bB1])
                                     + __half2float(KEh[j1 * 136 + bB1])) * 0.125f + mk1;
                rmax0 = fmaxf(rmax0, fmaxf(S[nt][0], S[nt][1]));
                rmax1 = fmaxf(rmax1, fmaxf(S[nt][2], S[nt][3]));
            }
            rmax0 = fmaxf(rmax0, __shfl_xor_sync(0xffffffffu, rmax0, 1));
            rmax0 = fmaxf(rmax0, __shfl_xor_sync(0xffffffffu, rmax0, 2));
            rmax1 = fmaxf(rmax1, __shfl_xor_sync(0xffffffffu, rmax1, 1));
            rmax1 = fmaxf(rmax1, __shfl_xor_sync(0xffffffffu, rmax1, 2));
            const float mn0 = fmaxf(mrow0, rmax0), mn1 = fmaxf(mrow1, rmax1);
            const float c0 = __expf(mrow0 - mn0), c1 = __expf(mrow1 - mn1);
            mrow0 = mn0; mrow1 = mn1;
            float ps0 = 0.f, ps1 = 0.f;
#pragma unroll
            for (int nt = 0; nt < 8; ++nt) {
                S[nt][0] = __expf(S[nt][0] - mn0); ps0 += S[nt][0];
                S[nt][1] = __expf(S[nt][1] - mn0); ps0 += S[nt][1];
                S[nt][2] = __expf(S[nt][2] - mn1); ps1 += S[nt][2];
                S[nt][3] = __expf(S[nt][3] - mn1); ps1 += S[nt][3];
            }
            ps0 += __shfl_xor_sync(0xffffffffu, ps0, 1);
            ps0 += __shfl_xor_sync(0xffffffffu, ps0, 2);
            ps1 += __shfl_xor_sync(0xffffffffu, ps1, 1);
            ps1 += __shfl_xor_sync(0xffffffffu, ps1, 2);
            lsum0 = lsum0 * c0 + ps0;
            lsum1 = lsum1 * c1 + ps1;
            if (t == 0) { corrs[iA] = c0; corrs[iB] = c1; }
            // P store fp16 into Ph (alias Eh, dead after sync3)
#pragma unroll
            for (int nt = 0; nt < 8; ++nt) {
                const int col = nt * 8 + 2 * t;
                *(__half2*)&Ph[iA * 72 + col] = __floats2half2_rn(S[nt][0], S[nt][1]);
                *(__half2*)&Ph[iB * 72 + col] = __floats2half2_rn(S[nt][2], S[nt][3]);
            }
        } else {
            // ---- B warps: stage V transposed fp16 into Vth (alias Kh),
            //      stride 68 halves, j-contiguous uint2 writes (conflict-free)
            const float* Vg = g_V + ((size_t)bh * SEQ + r0) * HD;
            const int tl = tid - 128;
#pragma unroll
            for (int it = 0; it < 8; ++it) {
                const int idx = tl + it * 128;
                const int cc = idx & 63, jg = idx >> 6;   // jg 0..15
                const float v0 = Vg[(jg * 4 + 0) * HD + cc];
                const float v1 = Vg[(jg * 4 + 1) * HD + cc];
                const float v2 = Vg[(jg * 4 + 2) * HD + cc];
                const float v3 = Vg[(jg * 4 + 3) * HD + cc];
                *(uint2*)&Vth[cc * 68 + jg * 4] =
                    make_uint2(h2u(v0, v1), h2u(v2, v3));
            }
        }
        __syncthreads();   // sync4: Ph, Vth, corrs ready

        // ---- PV (fp16): all warps, strip ms x n-half nh ----
        {
            const float cc0 = corrs[ms + g], cc1 = corrs[ms + g + 8];
#pragma unroll
            for (int nt = 0; nt < 4; ++nt) {
                acc[nt][0] *= cc0; acc[nt][1] *= cc0;
                acc[nt][2] *= cc1; acc[nt][3] *= cc1;
            }
#pragma unroll
            for (int ks = 0; ks < 4; ++ks) {
                const int kc = ks * 16 + 2 * t;
                uint32_t a[4];
                const __half* ap = Ph + (ms + g) * 72 + kc;
                a[0] = *(const uint32_t*)(ap);
                a[1] = *(const uint32_t*)(ap + 8 * 72);
                a[2] = *(const uint32_t*)(ap + 8);
                a[3] = *(const uint32_t*)(ap + 8 * 72 + 8);
#pragma unroll
                for (int nt = 0; nt < 4; ++nt) {
                    const __half* bp = Vth + (nh + nt * 8 + g) * 68 + kc;
                    uint32_t bb[2] = {*(const uint32_t*)(bp),
                                      *(const uint32_t*)(bp + 8)};
                    mma16n8k16h(acc[nt], a, bb);
                }
            }
        }
    }

    if (isA && t == 0) { lsums[ms + g] = lsum0; lsums[ms + g + 8] = lsum1; }
    __syncthreads();

    {
        const float inv0 = 1.f / lsums[ms + g];
        const float inv1 = 1.f / lsums[ms + g + 8];
        const int row0 = l0 + ms + g, row1 = row0 + 8;
#pragma unroll
        for (int nt = 0; nt < 4; ++nt) {
            const int col = hh * HD + nh + nt * 8 + 2 * t;
            *(float2*)(out + (size_t)(b * SEQ + row0) * HID + col) =
                make_float2(acc[nt][0] * inv0, acc[nt][1] * inv0);
            *(float2*)(out + (size_t)(b * SEQ + row1) * HID + col) =
                make_float2(acc[nt][2] * inv1, acc[nt][3] * inv1);
        }
    }
}

// ---------------------------------------------------------------------------
extern "C" void kernel_launch(void* const* d_in, const int* in_sizes, int n_in,
                              void* d_out, int out_size)
{
    (void)in_sizes; (void)n_in; (void)out_size;
    const float* hs   = (const float*)d_in[0];
    const float* w    = (const float*)d_in[1];
    const float* bias = (const float*)d_in[2];
    const float* emb  = (const float*)d_in[3];
    const float* mask = (const float*)d_in[4];
    float* out = (float*)d_out;

    cudaFuncSetAttribute(qkv_gemm_mma,
                         cudaFuncAttributeMaxDynamicSharedMemorySize, QG_SMEM_B);
    qkv_gemm_mma<<<dim3(HID * 3 / 128, BATCH * SEQ / 128), 256, QG_SMEM_B>>>(hs, w, bias);

    cudaFuncSetAttribute(attn_mma,
                         cudaFuncAttributeMaxDynamicSharedMemorySize, AT_SMEM_B);
    attn_mma<<<dim3(SEQ / 64, BATCH * NH), 256, AT_SMEM_B>>>(emb, mask, out);
}

// round 11
// speedup vs baseline: 3.4703x; 1.1001x over previous
#include <cuda_runtime.h>
#include <cuda_fp16.h>
#include <math_constants.h>
#include <cstdint>

#define NH    16
#define HD    64
#define SEQ   1024
#define BATCH 4
#define HID   1024

// fp16 scratch: Q/K row-major [bh][s][d]; V transposed [bh][d][s]; emb fp16
__device__ __half g_Qh[BATCH * NH * SEQ * HD];
__device__ __half g_Kh[BATCH * NH * SEQ * HD];
__device__ __half g_Vt[BATCH * NH * HD * SEQ];
__device__ __half emb_h[2047 * HD];

__device__ __forceinline__ uint32_t h2u(float x, float y) {
    __half2 h = __floats2half2_rn(x, y);
    return *(uint32_t*)&h;
}

__device__ __forceinline__ void mma16n8k16h(float c[4], const uint32_t a[4],
                                            const uint32_t b[2]) {
    asm volatile(
        "mma.sync.aligned.m16n8k16.row.col.f32.f16.f16.f32 "
        "{%0,%1,%2,%3}, {%4,%5,%6,%7}, {%8,%9}, {%0,%1,%2,%3};"
        : "+f"(c[0]), "+f"(c[1]), "+f"(c[2]), "+f"(c[3])
        : "r"(a[0]), "r"(a[1]), "r"(a[2]), "r"(a[3]), "r"(b[0]), "r"(b[1]));
}

// ===========================================================================
// Kernel 0: one-time dist_emb -> fp16
// ===========================================================================
__global__ void emb2h(const float* __restrict__ emb)
{
    const int i4 = blockIdx.x * 256 + threadIdx.x;   // element quad
    if (i4 * 4 < 2047 * HD) {
        const float4 v = *(const float4*)(emb + i4 * 4);
        *(uint2*)&emb_h[i4 * 4] = make_uint2(h2u(v.x, v.y), h2u(v.z, v.w));
    }
}

// ===========================================================================
// Kernel 1: fused QKV projection, fp16 mma, fp16 outputs (V pre-transposed)
// ===========================================================================
#define SSTH 40
#define QH_TILE (128 * SSTH)
#define QG_SMEM_B (4 * QH_TILE * 2)

__global__ __launch_bounds__(256) void qkv_gemm_mma(
    const float* __restrict__ hs,
    const float* __restrict__ w,
    const float* __restrict__ bias)
{
    extern __shared__ __align__(16) __half smh[];
    __half* As = smh;
    __half* Bs = smh + 2 * QH_TILE;

    const int tid  = threadIdx.x;
    const int m0   = blockIdx.y * 128;
    const int n0   = blockIdx.x * 128;
    const int lrow = tid >> 3;
    const int lc4  = tid & 7;

    const int lane = tid & 31, g = lane >> 2, t = lane & 3;
    const int wid  = tid >> 5, wm = wid >> 2, wn = wid & 3;

    float4 ra[4], rb[4];

#pragma unroll
    for (int it = 0; it < 4; ++it) {
        const int row = lrow + it * 32;
        ra[it] = *(const float4*)(hs + (size_t)(m0 + row) * HID + lc4 * 4);
        rb[it] = *(const float4*)(w  + (size_t)(n0 + row) * HID + lc4 * 4);
    }
#pragma unroll
    for (int it = 0; it < 4; ++it) {
        const int row = lrow + it * 32;
        *(uint2*)&As[row * SSTH + lc4 * 4] =
            make_uint2(h2u(ra[it].x, ra[it].y), h2u(ra[it].z, ra[it].w));
        *(uint2*)&Bs[row * SSTH + lc4 * 4] =
            make_uint2(h2u(rb[it].x, rb[it].y), h2u(rb[it].z, rb[it].w));
    }
    __syncthreads();

    float c[4][4][4];
#pragma unroll
    for (int mi = 0; mi < 4; ++mi)
#pragma unroll
        for (int ni = 0; ni < 4; ++ni)
#pragma unroll
            for (int r = 0; r < 4; ++r) c[mi][ni][r] = 0.f;

    for (int ch = 0; ch < 32; ++ch) {
        const int p = ch & 1;
        if (ch < 31) {
            const int k0 = (ch + 1) * 32;
#pragma unroll
            for (int it = 0; it < 4; ++it) {
                const int row = lrow + it * 32;
                ra[it] = *(const float4*)(hs + (size_t)(m0 + row) * HID + k0 + lc4 * 4);
                rb[it] = *(const float4*)(w  + (size_t)(n0 + row) * HID + k0 + lc4 * 4);
            }
        }

        const __half* Ab = As + p * QH_TILE;
        const __half* Bb = Bs + p * QH_TILE;
#pragma unroll
        for (int ks = 0; ks < 2; ++ks) {
            const int kc = ks * 16 + 2 * t;
            uint32_t a[4][4], b[4][2];
#pragma unroll
            for (int mi = 0; mi < 4; ++mi) {
                const __half* ap = Ab + (wm * 64 + mi * 16 + g) * SSTH + kc;
                a[mi][0] = *(const uint32_t*)(ap);
                a[mi][1] = *(const uint32_t*)(ap + 8 * SSTH);
                a[mi][2] = *(const uint32_t*)(ap + 8);
                a[mi][3] = *(const uint32_t*)(ap + 8 * SSTH + 8);
            }
#pragma unroll
            for (int ni = 0; ni < 4; ++ni) {
                const __half* bp = Bb + (wn * 32 + ni * 8 + g) * SSTH + kc;
                b[ni][0] = *(const uint32_t*)(bp);
                b[ni][1] = *(const uint32_t*)(bp + 8);
            }
#pragma unroll
            for (int mi = 0; mi < 4; ++mi)
#pragma unroll
                for (int ni = 0; ni < 4; ++ni)
                    mma16n8k16h(c[mi][ni], a[mi], b[ni]);
        }

        if (ch < 31) {
            __half* An = As + ((ch + 1) & 1) * QH_TILE;
            __half* Bn = Bs + ((ch + 1) & 1) * QH_TILE;
#pragma unroll
            for (int it = 0; it < 4; ++it) {
                const int row = lrow + it * 32;
                *(uint2*)&An[row * SSTH + lc4 * 4] =
                    make_uint2(h2u(ra[it].x, ra[it].y), h2u(ra[it].z, ra[it].w));
                *(uint2*)&Bn[row * SSTH + lc4 * 4] =
                    make_uint2(h2u(rb[it].x, rb[it].y), h2u(rb[it].z, rb[it].w));
            }
        }
        __syncthreads();
    }

    const int tsel = n0 >> 10;
    if (tsel < 2) {
        __half* dst = (tsel == 0) ? g_Qh : g_Kh;
#pragma unroll
        for (int mi = 0; mi < 4; ++mi) {
            const int m  = m0 + wm * 64 + mi * 16 + g;
            const int bb = m >> 10;
            const int s  = m & 1023;
#pragma unroll
            for (int ni = 0; ni < 4; ++ni) {
                const int gn  = n0 + wn * 32 + ni * 8 + t * 2;
                const int rem = gn & 1023;
                const int hh  = rem >> 6;
                const int dd  = rem & 63;
                const float2 bi = *(const float2*)(bias + gn);
                __half* base = dst + ((size_t)(bb * NH + hh) * SEQ + s) * HD + dd;
                *(uint32_t*)(base) = h2u(c[mi][ni][0] + bi.x, c[mi][ni][1] + bi.y);
                *(uint32_t*)(base + 8 * HD) = h2u(c[mi][ni][2] + bi.x, c[mi][ni][3] + bi.y);
            }
        }
    } else {
        // V: transposed scatter into g_Vt[bh][d][s]
#pragma unroll
        for (int mi = 0; mi < 4; ++mi) {
            const int m  = m0 + wm * 64 + mi * 16 + g;
            const int bb = m >> 10;
            const int s  = m & 1023;
#pragma unroll
            for (int ni = 0; ni < 4; ++ni) {
                const int gn  = n0 + wn * 32 + ni * 8 + t * 2;
                const int rem = gn & 1023;
                const int hh  = rem >> 6;
                const int dd  = rem & 63;
                const float2 bi = *(const float2*)(bias + gn);
                __half* base = g_Vt + ((size_t)(bb * NH + hh) * HD + dd) * SEQ + s;
                base[0]       = __float2half(c[mi][ni][0] + bi.x);
                base[SEQ]     = __float2half(c[mi][ni][1] + bi.y);
                base[8]       = __float2half(c[mi][ni][2] + bi.x);
                base[SEQ + 8] = __float2half(c[mi][ni][3] + bi.y);
            }
        }
    }
}

// ===========================================================================
// Kernel 2: attention, all-fp16 mma; staging is raw uint4 copies (no cvt).
// Warps 0-3 (A): QE + QK + softmax + P.  Warps 4-7 (B): KE + Vt copy.
// All warps: PV.  smem 72448 B -> 2 blocks/SM.
// ===========================================================================
#define AT_SMEM_B 72448

__global__ __launch_bounds__(256, 2) void attn_mma(
    const float* __restrict__ mask,
    float* __restrict__ out)
{
    extern __shared__ __align__(16) float sm2[];
    __half* Qh    = (__half*)sm2;             // [64][72]
    __half* Kh    = (__half*)(sm2 + 2304);    // [64][72] (Vth alias, stride 72)
    __half* Vth   = Kh;
    __half* Eh    = (__half*)(sm2 + 4608);    // [128][72] (Ph alias [64][72])
    __half* Ph    = Eh;
    __half* QEh   = (__half*)(sm2 + 9216);    // [64][136]
    __half* KEh   = (__half*)(sm2 + 13568);   // [64][136]
    float*  corrs = sm2 + 17920;              // [64]
    float*  lsums = sm2 + 17984;              // [64]
    float*  maskS = sm2 + 18048;              // [64]

    const int tid  = threadIdx.x;
    const int lane = tid & 31, g = lane >> 2, t = lane & 3;
    const int wid  = tid >> 5;
    const int ms   = (wid & 3) * 16;          // 16-row strip
    const int nh   = (wid >> 2) * 32;         // n-half for PV
    const bool isA = (wid < 4);
    const int bh = blockIdx.y, b = bh >> 4, hh = bh & 15;
    const int l0 = blockIdx.x * 64;

    // ---- stage Q (raw fp16 copy) ----
    const __half* Qg = g_Qh + ((size_t)bh * SEQ + l0) * HD;
#pragma unroll
    for (int it = 0; it < 2; ++it) {
        const int cidx = tid + it * 256;          // 512 uint4 chunks
        const int row = cidx >> 3, c16 = cidx & 7;
        *(uint4*)&Qh[row * 72 + c16 * 8] = *(const uint4*)(Qg + row * 64 + c16 * 8);
    }

    float mrow0 = -CUDART_INF_F, mrow1 = -CUDART_INF_F;
    float lsum0 = 0.f, lsum1 = 0.f;
    float acc[4][4];
#pragma unroll
    for (int nt = 0; nt < 4; ++nt)
#pragma unroll
        for (int r = 0; r < 4; ++r) acc[nt][r] = 0.f;

    float S[8][4];
    const int ebase = isA ? ms : (48 - ms);   // band start col for QE / KE

    for (int r0 = 0; r0 < SEQ; r0 += 64) {
        const int gb_ = l0 - r0 + 960;

        __syncthreads();   // sync1: prior PV reads (Ph, Vth) done
        // ---- stage K, E band (raw fp16 copies), mask ----
        const __half* Kg = g_Kh + ((size_t)bh * SEQ + r0) * HD;
#pragma unroll
        for (int it = 0; it < 2; ++it) {
            const int cidx = tid + it * 256;
            const int row = cidx >> 3, c16 = cidx & 7;
            *(uint4*)&Kh[row * 72 + c16 * 8] = *(const uint4*)(Kg + row * 64 + c16 * 8);
        }
#pragma unroll
        for (int it = 0; it < 4; ++it) {
            const int cidx = tid + it * 256;          // 1024 chunks
            const int row = cidx >> 3, c16 = cidx & 7;
            const int er = min(gb_ + row, 2046);
            *(uint4*)&Eh[row * 72 + c16 * 8] = *(const uint4*)(emb_h + er * 64 + c16 * 8);
        }
        if (tid < 16)
            *(float4*)&maskS[tid * 4] = *(const float4*)(mask + b * SEQ + r0 + tid * 4);
        __syncthreads();   // sync2: operands ready

        // ---- fp16 band GEMM: QE (A warps) / KE (B warps), 10 n8 tiles ----
        {
            const __half* Ah = isA ? Qh : Kh;
            __half* dstT = isA ? QEh : KEh;
#pragma unroll
            for (int c5 = 0; c5 < 2; ++c5) {
                float qe[5][4];
#pragma unroll
                for (int nt = 0; nt < 5; ++nt)
#pragma unroll
                    for (int r = 0; r < 4; ++r) qe[nt][r] = 0.f;
#pragma unroll
                for (int ks = 0; ks < 4; ++ks) {
                    const int kc = ks * 16 + 2 * t;
                    uint32_t a[4];
                    const __half* ap = Ah + (ms + g) * 72 + kc;
                    a[0] = *(const uint32_t*)(ap);
                    a[1] = *(const uint32_t*)(ap + 8 * 72);
                    a[2] = *(const uint32_t*)(ap + 8);
                    a[3] = *(const uint32_t*)(ap + 8 * 72 + 8);
#pragma unroll
                    for (int nt = 0; nt < 5; ++nt) {
                        const int col = ebase + (c5 * 5 + nt) * 8;
                        const __half* bp = Eh + (col + g) * 72 + kc;
                        uint32_t bb[2] = {*(const uint32_t*)(bp),
                                          *(const uint32_t*)(bp + 8)};
                        mma16n8k16h(qe[nt], a, bb);
                    }
                }
#pragma unroll
                for (int nt = 0; nt < 5; ++nt) {
                    const int col = ebase + (c5 * 5 + nt) * 8 + 2 * t;
                    *(__half2*)&dstT[(ms + g) * 136 + col] =
                        __floats2half2_rn(qe[nt][0], qe[nt][1]);
                    *(__half2*)&dstT[(ms + g + 8) * 136 + col] =
                        __floats2half2_rn(qe[nt][2], qe[nt][3]);
                }
            }
        }
        if (isA) {
            // ---- QK (fp16, k=16) ----
#pragma unroll
            for (int nt = 0; nt < 8; ++nt)
#pragma unroll
                for (int r = 0; r < 4; ++r) S[nt][r] = 0.f;
#pragma unroll
            for (int ks = 0; ks < 4; ++ks) {
                const int kc = ks * 16 + 2 * t;
                uint32_t a[4];
                const __half* ap = Qh + (ms + g) * 72 + kc;
                a[0] = *(const uint32_t*)(ap);
                a[1] = *(const uint32_t*)(ap + 8 * 72);
                a[2] = *(const uint32_t*)(ap + 8);
                a[3] = *(const uint32_t*)(ap + 8 * 72 + 8);
#pragma unroll
                for (int nt = 0; nt < 8; ++nt) {
                    const __half* bp = Kh + (nt * 8 + g) * 72 + kc;
                    uint32_t bb[2] = {*(const uint32_t*)(bp),
                                      *(const uint32_t*)(bp + 8)};
                    mma16n8k16h(S[nt], a, bb);
                }
            }
        }
        __syncthreads();   // sync3: QEh/KEh done; Kh/Eh mma reads done

        if (isA) {
            // ---- gather + scale + mask + online softmax + P store (fp16) ----
            const int iA = ms + g, iB = ms + g + 8;
            float rmax0 = -CUDART_INF_F, rmax1 = -CUDART_INF_F;
#pragma unroll
            for (int nt = 0; nt < 8; ++nt) {
                const int j0 = nt * 8 + 2 * t, j1 = j0 + 1;
                const float mk0 = maskS[j0], mk1 = maskS[j1];
                const int bA0 = iA - j0 + 63, bA1 = iA - j1 + 63;
                const int bB0 = iB - j0 + 63, bB1 = iB - j1 + 63;
                S[nt][0] = (S[nt][0] + __half2float(QEh[iA * 136 + bA0])
                                     + __half2float(KEh[j0 * 136 + bA0])) * 0.125f + mk0;
                S[nt][1] = (S[nt][1] + __half2float(QEh[iA * 136 + bA1])
                                     + __half2float(KEh[j1 * 136 + bA1])) * 0.125f + mk1;
                S[nt][2] = (S[nt][2] + __half2float(QEh[iB * 136 + bB0])
                                     + __half2float(KEh[j0 * 136 + bB0])) * 0.125f + mk0;
                S[nt][3] = (S[nt][3] + __half2float(QEh[iB * 136 + bB1])
                                     + __half2float(KEh[j1 * 136 + bB1])) * 0.125f + mk1;
                rmax0 = fmaxf(rmax0, fmaxf(S[nt][0], S[nt][1]));
                rmax1 = fmaxf(rmax1, fmaxf(S[nt][2], S[nt][3]));
            }
            rmax0 = fmaxf(rmax0, __shfl_xor_sync(0xffffffffu, rmax0, 1));
            rmax0 = fmaxf(rmax0, __shfl_xor_sync(0xffffffffu, rmax0, 2));
            rmax1 = fmaxf(rmax1, __shfl_xor_sync(0xffffffffu, rmax1, 1));
            rmax1 = fmaxf(rmax1, __shfl_xor_sync(0xffffffffu, rmax1, 2));
            const float mn0 = fmaxf(mrow0, rmax0), mn1 = fmaxf(mrow1, rmax1);
            const float c0 = __expf(mrow0 - mn0), c1 = __expf(mrow1 - mn1);
            mrow0 = mn0; mrow1 = mn1;
            float ps0 = 0.f, ps1 = 0.f;
#pragma unroll
            for (int nt = 0; nt < 8; ++nt) {
                S[nt][0] = __expf(S[nt][0] - mn0); ps0 += S[nt][0];
                S[nt][1] = __expf(S[nt][1] - mn0); ps0 += S[nt][1];
                S[nt][2] = __expf(S[nt][2] - mn1); ps1 += S[nt][2];
                S[nt][3] = __expf(S[nt][3] - mn1); ps1 += S[nt][3];
            }
            ps0 += __shfl_xor_sync(0xffffffffu, ps0, 1);
            ps0 += __shfl_xor_sync(0xffffffffu, ps0, 2);
            ps1 += __shfl_xor_sync(0xffffffffu, ps1, 1);
            ps1 += __shfl_xor_sync(0xffffffffu, ps1, 2);
            lsum0 = lsum0 * c0 + ps0;
            lsum1 = lsum1 * c1 + ps1;
            if (t == 0) { corrs[iA] = c0; corrs[iB] = c1; }
            // P store fp16 into Ph (alias Eh, dead after sync3)
#pragma unroll
            for (int nt = 0; nt < 8; ++nt) {
                const int col = nt * 8 + 2 * t;
                *(__half2*)&Ph[iA * 72 + col] = __floats2half2_rn(S[nt][0], S[nt][1]);
                *(__half2*)&Ph[iB * 72 + col] = __floats2half2_rn(S[nt][2], S[nt][3]);
            }
        } else {
            // ---- B warps: copy pre-transposed V tile (raw fp16, coalesced) ----
            const __half* Vg = g_Vt + (size_t)bh * HD * SEQ + r0;
            const int tl = tid - 128;
#pragma unroll
            for (int it = 0; it < 4; ++it) {
                const int cidx = tl + it * 128;       // 512 uint4 chunks
                const int dd = cidx >> 3, c16 = cidx & 7;
                *(uint4*)&Vth[dd * 72 + c16 * 8] =
                    *(const uint4*)(Vg + (size_t)dd * SEQ + c16 * 8);
            }
        }
        __syncthreads();   // sync4: Ph, Vth, corrs ready

        // ---- PV (fp16): all warps, strip ms x n-half nh ----
        {
            const float cc0 = corrs[ms + g], cc1 = corrs[ms + g + 8];
#pragma unroll
            for (int nt = 0; nt < 4; ++nt) {
                acc[nt][0] *= cc0; acc[nt][1] *= cc0;
                acc[nt][2] *= cc1; acc[nt][3] *= cc1;
            }
#pragma unroll
            for (int ks = 0; ks < 4; ++ks) {
                const int kc = ks * 16 + 2 * t;
                uint32_t a[4];
                const __half* ap = Ph + (ms + g) * 72 + kc;
                a[0] = *(const uint32_t*)(ap);
                a[1] = *(const uint32_t*)(ap + 8 * 72);
                a[2] = *(const uint32_t*)(ap + 8);
                a[3] = *(const uint32_t*)(ap + 8 * 72 + 8);
#pragma unroll
                for (int nt = 0; nt < 4; ++nt) {
                    const __half* bp = Vth + (nh + nt * 8 + g) * 72 + kc;
                    uint32_t bb[2] = {*(const uint32_t*)(bp),
                                      *(const uint32_t*)(bp + 8)};
                    mma16n8k16h(acc[nt], a, bb);
                }
            }
        }
    }

    if (isA && t == 0) { lsums[ms + g] = lsum0; lsums[ms + g + 8] = lsum1; }
    __syncthreads();

    {
        const float inv0 = 1.f / lsums[ms + g];
        const float inv1 = 1.f / lsums[ms + g + 8];
        const int row0 = l0 + ms + g, row1 = row0 + 8;
#pragma unroll
        for (int nt = 0; nt < 4; ++nt) {
            const int col = hh * HD + nh + nt * 8 + 2 * t;
            *(float2*)(out + (size_t)(b * SEQ + row0) * HID + col) =
                make_float2(acc[nt][0] * inv0, acc[nt][1] * inv0);
            *(float2*)(out + (size_t)(b * SEQ + row1) * HID + col) =
                make_float2(acc[nt][2] * inv1, acc[nt][3] * inv1);
        }
    }
}

// ---------------------------------------------------------------------------
extern "C" void kernel_launch(void* const* d_in, const int* in_sizes, int n_in,
                              void* d_out, int out_size)
{
    (void)in_sizes; (void)n_in; (void)out_size;
    const float* hs   = (const float*)d_in[0];
    const float* w    = (const float*)d_in[1];
    const float* bias = (const float*)d_in[2];
    const float* emb  = (const float*)d_in[3];
    const float* mask = (const float*)d_in[4];
    float* out = (float*)d_out;

    emb2h<<<(2047 * HD / 4 + 255) / 256, 256>>>(emb);

    cudaFuncSetAttribute(qkv_gemm_mma,
                         cudaFuncAttributeMaxDynamicSharedMemorySize, QG_SMEM_B);
    qkv_gemm_mma<<<dim3(HID * 3 / 128, BATCH * SEQ / 128), 256, QG_SMEM_B>>>(hs, w, bias);

    cudaFuncSetAttribute(attn_mma,
                         cudaFuncAttributeMaxDynamicSharedMemorySize, AT_SMEM_B);
    attn_mma<<<dim3(SEQ / 64, BATCH * NH), 256, AT_SMEM_B>>>(mask, out);
}